// round 1
// baseline (speedup 1.0000x reference)
#include <cuda_runtime.h>

#define NN 100000
#define EE 1000000

// ---------------- scratch (__device__ globals; no allocation allowed) ----------------
__device__ float g_hs[6][NN * 128];     // projected src features per (rel, scale)
__device__ float g_agg[6][NN * 128];    // normalized aggregation per (rel, scale)
__device__ float g_asP[3][NN * 8];      // a_src packed [node][local h0..3, global h0..3]
__device__ float g_adP[3][NN * 8];      // a_dst packed
__device__ float g_vpack[3 * 2 * 8 * 128]; // folded W·att vectors: [(rel*2+side)][j][k]
__device__ int   g_deg[3][NN];
__device__ int   g_cur[3][NN];
__device__ int   g_off[3][NN + 1];
__device__ int   g_part[3][256];
__device__ int   g_csr[3][EE + NN];
__device__ float g_cat[2][NN * 256];    // [loc | glb] per dst type
__device__ float g_gl[2][NN * 128];     // gate linear
__device__ float g_fus[2][NN * 128];    // fused features

// ---------------- helpers ----------------
__device__ __forceinline__ float2 ffma2(float2 a, float2 b, float2 c) {
    unsigned long long ua = *reinterpret_cast<unsigned long long*>(&a);
    unsigned long long ub = *reinterpret_cast<unsigned long long*>(&b);
    unsigned long long uc = *reinterpret_cast<unsigned long long*>(&c);
    asm("fma.rn.f32x2 %0, %1, %2, %0;" : "+l"(uc) : "l"(ua), "l"(ub));
    return *reinterpret_cast<float2*>(&uc);
}

// ---------------- fold W·att into per-(rel,side,scale,head) vectors ----------------
__global__ void prep_v_kernel(const float* __restrict__ Wsl, const float* __restrict__ Wsg,
                              const float* __restrict__ Wdl, const float* __restrict__ Wdg,
                              const float* __restrict__ asl, const float* __restrict__ asg,
                              const float* __restrict__ adl, const float* __restrict__ adg) {
    int idx = blockIdx.x * blockDim.x + threadIdx.x;
    if (idx >= 3 * 2 * 2 * 128 * 4) return;
    int h = idx & 3, k = (idx >> 2) & 127, sc = (idx >> 9) & 1, side = (idx >> 10) & 1, rel = idx >> 11;
    const float* W; const float* att;
    if (side == 0) { W = sc ? Wsg : Wsl; att = sc ? asg : asl; }
    else           { W = sc ? Wdg : Wdl; att = sc ? adg : adl; }
    W += (size_t)rel * 128 * 128;
    att += rel * 4 * 32;
    float s = 0.f;
#pragma unroll
    for (int c = 0; c < 32; c++) s += W[k * 128 + h * 32 + c] * att[h * 32 + c];
    // transposed layout: j (=sc*4+h) slow, k fast -> coalesced float4 reads later
    g_vpack[((rel * 2 + side) * 8 + sc * 4 + h) * 128 + k] = s;
}

// ---------------- a = x @ v  (warp per node) ----------------
__global__ void compute_a_kernel(const float* __restrict__ x, int rel, int side) {
    int node = (blockIdx.x * blockDim.x + threadIdx.x) >> 5;
    int lane = threadIdx.x & 31;
    if (node >= NN) return;
    const float* vp = &g_vpack[(size_t)(rel * 2 + side) * 8 * 128];
    float4 x4 = *reinterpret_cast<const float4*>(&x[(size_t)node * 128 + lane * 4]);
    float p[8];
#pragma unroll
    for (int j = 0; j < 8; j++) {
        float4 v4 = *reinterpret_cast<const float4*>(&vp[j * 128 + lane * 4]);
        p[j] = x4.x * v4.x + x4.y * v4.y + x4.z * v4.z + x4.w * v4.w;
    }
#pragma unroll
    for (int d = 16; d > 0; d >>= 1)
#pragma unroll
        for (int j = 0; j < 8; j++) p[j] += __shfl_xor_sync(0xffffffffu, p[j], d);
    float* out = (side == 0) ? &g_asP[rel][0] : &g_adP[rel][0];
    if (lane < 8) out[(size_t)node * 8 + lane] = p[lane];
}

// ---------------- generic fp32 GEMM: C[M,128] = A[M,K] @ B[K,128] ----------------
__global__ __launch_bounds__(256) void gemm_kernel(const float* __restrict__ A,
                                                   const float* __restrict__ B,
                                                   float* __restrict__ C, int M, int K) {
    __shared__ float As[32][68];   // [k][m], BM=64 + pad
    __shared__ float Bs[32][132];  // [k][n], BN=128 + pad
    const int tid = threadIdx.x;
    const int tx = tid & 15, ty = tid >> 4;
    const int m0 = blockIdx.x * 64;
    float2 acc[4][4];
#pragma unroll
    for (int r = 0; r < 4; r++)
#pragma unroll
        for (int c = 0; c < 4; c++) acc[r][c] = make_float2(0.f, 0.f);

    for (int k0 = 0; k0 < K; k0 += 32) {
#pragma unroll
        for (int j = 0; j < 2; j++) {               // A tile 64x32
            int i = tid + j * 256;
            int r = i >> 3, kv = i & 7;
            float4 v = make_float4(0.f, 0.f, 0.f, 0.f);
            if (m0 + r < M)
                v = *reinterpret_cast<const float4*>(&A[(size_t)(m0 + r) * K + k0 + kv * 4]);
            As[kv * 4 + 0][r] = v.x; As[kv * 4 + 1][r] = v.y;
            As[kv * 4 + 2][r] = v.z; As[kv * 4 + 3][r] = v.w;
        }
#pragma unroll
        for (int j = 0; j < 4; j++) {               // B tile 32x128
            int i = tid + j * 256;
            int r = i >> 5, c4 = i & 31;
            float4 v = *reinterpret_cast<const float4*>(&B[(size_t)(k0 + r) * 128 + c4 * 4]);
            *reinterpret_cast<float4*>(&Bs[r][c4 * 4]) = v;
        }
        __syncthreads();
#pragma unroll
        for (int k = 0; k < 32; k++) {
            float4 a  = *reinterpret_cast<const float4*>(&As[k][ty * 4]);
            float4 b0 = *reinterpret_cast<const float4*>(&Bs[k][tx * 8]);
            float4 b1 = *reinterpret_cast<const float4*>(&Bs[k][tx * 8 + 4]);
            float2 aa[4] = {{a.x, a.x}, {a.y, a.y}, {a.z, a.z}, {a.w, a.w}};
            float2 bb[4] = {{b0.x, b0.y}, {b0.z, b0.w}, {b1.x, b1.y}, {b1.z, b1.w}};
#pragma unroll
            for (int r = 0; r < 4; r++)
#pragma unroll
                for (int c = 0; c < 4; c++) acc[r][c] = ffma2(aa[r], bb[c], acc[r][c]);
        }
        __syncthreads();
    }
#pragma unroll
    for (int r = 0; r < 4; r++) {
        int row = m0 + ty * 4 + r;
        if (row < M) {
            float4 o0 = make_float4(acc[r][0].x, acc[r][0].y, acc[r][1].x, acc[r][1].y);
            float4 o1 = make_float4(acc[r][2].x, acc[r][2].y, acc[r][3].x, acc[r][3].y);
            *reinterpret_cast<float4*>(&C[(size_t)row * 128 + tx * 8]) = o0;
            *reinterpret_cast<float4*>(&C[(size_t)row * 128 + tx * 8 + 4]) = o1;
        }
    }
}

// ---------------- CSR build ----------------
__global__ void zero_kernel(int rel) {
    int i = blockIdx.x * blockDim.x + threadIdx.x;
    if (i < NN) { g_deg[rel][i] = 0; g_cur[rel][i] = 0; }
}
__global__ void count_kernel(const int* __restrict__ ei, int Etot, int rel) {
    int i = blockIdx.x * blockDim.x + threadIdx.x;
    if (i >= Etot) return;
    int d = (i < EE) ? ei[EE + i] : (i - EE);   // idx >= EE: self loop
    atomicAdd(&g_deg[rel][d], 1);
}
__global__ void scan1_kernel(int rel) {
    __shared__ int s[1024];
    int tid = threadIdx.x;
    int i = blockIdx.x * 1024 + tid;
    int v = (i < NN) ? g_deg[rel][i] : 0;
    s[tid] = v; __syncthreads();
    for (int d = 1; d < 1024; d <<= 1) {
        int t = (tid >= d) ? s[tid - d] : 0;
        __syncthreads();
        s[tid] += t; __syncthreads();
    }
    if (i < NN) g_off[rel][i] = s[tid] - v;     // exclusive
    if (tid == 1023) g_part[rel][blockIdx.x] = s[1023];
}
__global__ void scan2_kernel(int rel, int P) {
    __shared__ int s[128];
    int tid = threadIdx.x;
    int v = (tid < P) ? g_part[rel][tid] : 0;
    s[tid] = v; __syncthreads();
    for (int d = 1; d < 128; d <<= 1) {
        int t = (tid >= d) ? s[tid - d] : 0;
        __syncthreads();
        s[tid] += t; __syncthreads();
    }
    if (tid < P) g_part[rel][tid] = s[tid] - v;
    if (tid == 127) g_off[rel][NN] = s[127];
}
__global__ void scan3_kernel(int rel) {
    int i = blockIdx.x * 1024 + threadIdx.x;
    if (i < NN) g_off[rel][i] += g_part[rel][blockIdx.x];
}
__global__ void fill_kernel(const int* __restrict__ ei, int Etot, int rel) {
    int i = blockIdx.x * blockDim.x + threadIdx.x;
    if (i >= Etot) return;
    int s, d;
    if (i < EE) { s = ei[i]; d = ei[EE + i]; } else { s = d = i - EE; }
    int pos = atomicAdd(&g_cur[rel][d], 1);
    g_csr[rel][g_off[rel][d] + pos] = s;
}

// ---------------- softmax-attention aggregation: warp per dst node ----------------
__global__ void agg_kernel(int rel) {
    int node = blockIdx.x * 8 + (threadIdx.x >> 5);
    int lane = threadIdx.x & 31;
    if (node >= NN) return;
    const float* __restrict__ hsL = g_hs[rel * 2 + 0];
    const float* __restrict__ hsG = g_hs[rel * 2 + 1];
    const int* __restrict__ csr = g_csr[rel];
    int beg = g_off[rel][node], end = g_off[rel][node + 1];
    float adv = (lane < 8) ? g_adP[rel][(size_t)node * 8 + lane] : 0.f;
    int h = lane >> 3;   // head owning channels [lane*4, lane*4+4)
    float4 aL = make_float4(0.f, 0.f, 0.f, 0.f);
    float4 aG = make_float4(0.f, 0.f, 0.f, 0.f);
    float dL = 0.f, dG = 0.f;
    for (int i = beg; i < end; i++) {
        int src = csr[i];
        float as = 0.f;
        if (lane < 8) as = __ldg(&g_asP[rel][(size_t)src * 8 + lane]);
        float sum8 = as + adv;
        float sL = __shfl_sync(0xffffffffu, sum8, h);
        float sG = __shfl_sync(0xffffffffu, sum8, 4 + h);
        float eL = sL > 0.f ? sL : 0.2f * sL;   // local leaky slope
        float eG = sG > 0.f ? sG : 0.3f * sG;   // global leaky slope
        float wL = __expf(eL), wG = __expf(eG); // max-shift dropped: ratio-invariant, e bounded
        dL += wL; dG += wG;
        float4 hl = *reinterpret_cast<const float4*>(&hsL[(size_t)src * 128 + lane * 4]);
        float4 hg = *reinterpret_cast<const float4*>(&hsG[(size_t)src * 128 + lane * 4]);
        aL.x += wL * hl.x; aL.y += wL * hl.y; aL.z += wL * hl.z; aL.w += wL * hl.w;
        aG.x += wG * hg.x; aG.y += wG * hg.y; aG.z += wG * hg.z; aG.w += wG * hg.w;
    }
    float iL = 1.f / (dL + 1e-16f), iG = 1.f / (dG + 1e-16f);
    float4 oL = make_float4(aL.x * iL, aL.y * iL, aL.z * iL, aL.w * iL);
    float4 oG = make_float4(aG.x * iG, aG.y * iG, aG.z * iG, aG.w * iG);
    *reinterpret_cast<float4*>(&g_agg[rel * 2 + 0][(size_t)node * 128 + lane * 4]) = oL;
    *reinterpret_cast<float4*>(&g_agg[rel * 2 + 1][(size_t)node * 128 + lane * 4]) = oG;
}

// ---------------- fuse path ----------------
__global__ void f1_user_kernel(const float* __restrict__ bl, const float* __restrict__ bg,
                               const float* __restrict__ gates) {
    size_t i = (size_t)blockIdx.x * blockDim.x + threadIdx.x;
    if (i >= (size_t)NN * 128) return;
    int c = (int)(i & 127);
    size_t n = i >> 7;
    float g0 = gates[0], g1 = gates[1];
    float m = fmaxf(g0, g1);
    float e0 = __expf(g0 - m), e1 = __expf(g1 - m);
    float inv = 1.f / (e0 + e1);
    float w0 = e0 * inv, w1 = e1 * inv;
    // rel1 (rev, agg idx 2/3) + rel2 (follows, agg idx 4/5), biases rel1->+128, rel2->+256
    float loc = w0 * (g_agg[2][i] + bl[128 + c]) + w1 * (g_agg[4][i] + bl[256 + c]);
    float glb = w0 * (g_agg[3][i] + bg[128 + c]) + w1 * (g_agg[5][i] + bg[256 + c]);
    g_cat[0][n * 256 + c] = loc;
    g_cat[0][n * 256 + 128 + c] = glb;
}
__global__ void f1_item_kernel(const float* __restrict__ bl, const float* __restrict__ bg) {
    size_t i = (size_t)blockIdx.x * blockDim.x + threadIdx.x;
    if (i >= (size_t)NN * 128) return;
    int c = (int)(i & 127);
    size_t n = i >> 7;
    float loc = g_agg[0][i] + bl[c];
    float glb = g_agg[1][i] + bg[c];
    g_cat[1][n * 256 + c] = loc;
    g_cat[1][n * 256 + 128 + c] = glb;
}
__global__ void f3_kernel(int t, const float* __restrict__ gb) {
    size_t i = (size_t)blockIdx.x * blockDim.x + threadIdx.x;
    if (i >= (size_t)NN * 128) return;
    int c = (int)(i & 127);
    size_t n = i >> 7;
    float x = g_gl[t][i] + gb[c];
    float s = 1.f / (1.f + __expf(-x));
    float loc = g_cat[t][n * 256 + c], glb = g_cat[t][n * 256 + 128 + c];
    g_fus[t][i] = s * loc + (1.f - s) * glb;
}

// ---------------- launch ----------------
extern "C" void kernel_launch(void* const* d_in, const int* in_sizes, int n_in,
                              void* d_out, int out_size) {
    const float* x_user = (const float*)d_in[0];
    const float* x_item = (const float*)d_in[1];
    const float* Wsl = (const float*)d_in[2];
    const float* Wdl = (const float*)d_in[3];
    const float* asl = (const float*)d_in[4];
    const float* adl = (const float*)d_in[5];
    const float* bl  = (const float*)d_in[6];
    const float* Wsg = (const float*)d_in[7];
    const float* Wdg = (const float*)d_in[8];
    const float* asg = (const float*)d_in[9];
    const float* adg = (const float*)d_in[10];
    const float* bg  = (const float*)d_in[11];
    const float* gW  = (const float*)d_in[12];
    const float* gb  = (const float*)d_in[13];
    const float* oW  = (const float*)d_in[14];
    const float* rg  = (const float*)d_in[15];
    const int* ei_buys    = (const int*)d_in[16];
    const int* ei_rev     = (const int*)d_in[17];
    const int* ei_follows = (const int*)d_in[18];
    float* out = (float*)d_out;

    float *hs_base, *cat_base, *gl_base, *fus_base;
    cudaGetSymbolAddress((void**)&hs_base, g_hs);
    cudaGetSymbolAddress((void**)&cat_base, g_cat);
    cudaGetSymbolAddress((void**)&gl_base, g_gl);
    cudaGetSymbolAddress((void**)&fus_base, g_fus);

    const int GA = (NN * 32 + 255) / 256;        // warp-per-node kernels
    const int GB = (NN + 63) / 64;               // GEMM row tiles
    const int GE = (NN * 128 + 255) / 256;       // elementwise
    const int GSCAN = (NN + 1023) / 1024;        // 98

    prep_v_kernel<<<(12288 + 255) / 256, 256>>>(Wsl, Wsg, Wdl, Wdg, asl, asg, adl, adg);

    // attention logits (src/dst per relation)
    compute_a_kernel<<<GA, 256>>>(x_user, 0, 0);
    compute_a_kernel<<<GA, 256>>>(x_item, 0, 1);
    compute_a_kernel<<<GA, 256>>>(x_item, 1, 0);
    compute_a_kernel<<<GA, 256>>>(x_user, 1, 1);
    compute_a_kernel<<<GA, 256>>>(x_user, 2, 0);
    compute_a_kernel<<<GA, 256>>>(x_user, 2, 1);

    // src projections hs (6 GEMMs)
    gemm_kernel<<<GB, 256>>>(x_user, Wsl + 0 * 16384, hs_base + (size_t)0 * NN * 128, NN, 128);
    gemm_kernel<<<GB, 256>>>(x_user, Wsg + 0 * 16384, hs_base + (size_t)1 * NN * 128, NN, 128);
    gemm_kernel<<<GB, 256>>>(x_item, Wsl + 1 * 16384, hs_base + (size_t)2 * NN * 128, NN, 128);
    gemm_kernel<<<GB, 256>>>(x_item, Wsg + 1 * 16384, hs_base + (size_t)3 * NN * 128, NN, 128);
    gemm_kernel<<<GB, 256>>>(x_user, Wsl + 2 * 16384, hs_base + (size_t)4 * NN * 128, NN, 128);
    gemm_kernel<<<GB, 256>>>(x_user, Wsg + 2 * 16384, hs_base + (size_t)5 * NN * 128, NN, 128);

    // per-relation CSR build + aggregation
    const int* eis[3] = {ei_buys, ei_rev, ei_follows};
    const int etot[3] = {EE, EE, EE + NN};
    for (int r = 0; r < 3; r++) {
        int Et = etot[r];
        zero_kernel<<<(NN + 255) / 256, 256>>>(r);
        count_kernel<<<(Et + 255) / 256, 256>>>(eis[r], Et, r);
        scan1_kernel<<<GSCAN, 1024>>>(r);
        scan2_kernel<<<1, 128>>>(r, GSCAN);
        scan3_kernel<<<GSCAN, 1024>>>(r);
        fill_kernel<<<(Et + 255) / 256, 256>>>(eis[r], Et, r);
        agg_kernel<<<(NN + 7) / 8, 256>>>(r);
    }

    // fuse
    f1_user_kernel<<<GE, 256>>>(bl, bg, rg);
    f1_item_kernel<<<GE, 256>>>(bl, bg);
    gemm_kernel<<<GB, 256>>>(cat_base + (size_t)0 * NN * 256, gW + 0 * 32768,
                             gl_base + (size_t)0 * NN * 128, NN, 256);
    gemm_kernel<<<GB, 256>>>(cat_base + (size_t)1 * NN * 256, gW + 1 * 32768,
                             gl_base + (size_t)1 * NN * 128, NN, 256);
    f3_kernel<<<GE, 256>>>(0, gb);
    f3_kernel<<<GE, 256>>>(1, gb + 128);
    gemm_kernel<<<GB, 256>>>(fus_base + (size_t)0 * NN * 128, oW + 0 * 16384, out, NN, 128);
    gemm_kernel<<<GB, 256>>>(fus_base + (size_t)1 * NN * 128, oW + 1 * 16384,
                             out + (size_t)NN * 128, NN, 128);
}

// round 2
// speedup vs baseline: 1.3594x; 1.3594x over previous
#include <cuda_runtime.h>
#include <cstdint>

#define NN 100000
#define EE 1000000

// ---------------- scratch (__device__ globals; no allocation allowed) ----------------
__device__ float g_hs[6][NN * 128];     // projected src features per (rel, scale)
__device__ float g_agg[6][NN * 128];    // normalized aggregation per (rel, scale)
__device__ float g_asP[3][NN * 8];      // a_src packed [node][local h0..3, global h0..3]
__device__ float g_adP[3][NN * 8];      // a_dst packed
__device__ float g_vpack[3 * 2 * 8 * 128]; // folded W·att vectors: [(rel*2+side)][j][k]
__device__ int   g_deg[3][NN];
__device__ int   g_cur[3][NN];
__device__ int   g_off[3][NN + 1];
__device__ int   g_part[3][256];
__device__ int   g_csr[3][EE + NN];
__device__ float g_cat[2][NN * 256];    // [loc | glb] per dst type
__device__ float g_gl[2][NN * 128];     // gate linear
__device__ float g_fus[2][NN * 128];    // fused features

// ---------------- helpers ----------------
__device__ __forceinline__ float tf32_rna(float x) {
    uint32_t u;
    asm("cvt.rna.tf32.f32 %0, %1;" : "=r"(u) : "f"(x));
    return __uint_as_float(u);
}

__device__ __forceinline__ void mma_tf32(float* d, const float* a, float b0, float b1) {
    asm volatile(
        "mma.sync.aligned.m16n8k8.row.col.f32.tf32.tf32.f32 "
        "{%0,%1,%2,%3}, {%4,%5,%6,%7}, {%8,%9}, {%0,%1,%2,%3};"
        : "+f"(d[0]), "+f"(d[1]), "+f"(d[2]), "+f"(d[3])
        : "r"(__float_as_uint(a[0])), "r"(__float_as_uint(a[1])),
          "r"(__float_as_uint(a[2])), "r"(__float_as_uint(a[3])),
          "r"(__float_as_uint(b0)), "r"(__float_as_uint(b1)));
}

// ---------------- fold W·att into per-(rel,side,scale,head) vectors ----------------
__global__ void prep_v_kernel(const float* __restrict__ Wsl, const float* __restrict__ Wsg,
                              const float* __restrict__ Wdl, const float* __restrict__ Wdg,
                              const float* __restrict__ asl, const float* __restrict__ asg,
                              const float* __restrict__ adl, const float* __restrict__ adg) {
    int idx = blockIdx.x * blockDim.x + threadIdx.x;
    if (idx >= 3 * 2 * 2 * 128 * 4) return;
    int h = idx & 3, k = (idx >> 2) & 127, sc = (idx >> 9) & 1, side = (idx >> 10) & 1, rel = idx >> 11;
    const float* W; const float* att;
    if (side == 0) { W = sc ? Wsg : Wsl; att = sc ? asg : asl; }
    else           { W = sc ? Wdg : Wdl; att = sc ? adg : adl; }
    W += (size_t)rel * 128 * 128;
    att += rel * 4 * 32;
    float s = 0.f;
#pragma unroll
    for (int c = 0; c < 32; c++) s += W[k * 128 + h * 32 + c] * att[h * 32 + c];
    g_vpack[((rel * 2 + side) * 8 + sc * 4 + h) * 128 + k] = s;
}

// ---------------- a = x @ v  (warp per node) ----------------
__global__ void compute_a_kernel(const float* __restrict__ x, int rel, int side) {
    int node = (blockIdx.x * blockDim.x + threadIdx.x) >> 5;
    int lane = threadIdx.x & 31;
    if (node >= NN) return;
    const float* vp = &g_vpack[(size_t)(rel * 2 + side) * 8 * 128];
    float4 x4 = *reinterpret_cast<const float4*>(&x[(size_t)node * 128 + lane * 4]);
    float p[8];
#pragma unroll
    for (int j = 0; j < 8; j++) {
        float4 v4 = *reinterpret_cast<const float4*>(&vp[j * 128 + lane * 4]);
        p[j] = x4.x * v4.x + x4.y * v4.y + x4.z * v4.z + x4.w * v4.w;
    }
#pragma unroll
    for (int d = 16; d > 0; d >>= 1)
#pragma unroll
        for (int j = 0; j < 8; j++) p[j] += __shfl_xor_sync(0xffffffffu, p[j], d);
    float* out = (side == 0) ? &g_asP[rel][0] : &g_adP[rel][0];
    if (lane < 8) out[(size_t)node * 8 + lane] = p[lane];
}

// ---------------- tf32 tensor-core GEMM (3xTF32): C[M,128] = A[M,K] @ B[K,128] ----------------
// CTA tile 128x128, BK=8, 8 warps of 64x32, double-buffered smem.
__global__ __launch_bounds__(256) void gemm_tf32_kernel(const float* __restrict__ A,
                                                        const float* __restrict__ B,
                                                        float* __restrict__ C, int M, int K) {
    __shared__ float Ah[2][8][136], Al[2][8][136];
    __shared__ float Bh[2][8][136], Bl[2][8][136];
    const int tid = threadIdx.x;
    const int lane = tid & 31, warp = tid >> 5;
    const int wm = warp >> 2, wn = warp & 3;      // warp grid 2x4
    const int gr = lane >> 2, gk = lane & 3;      // mma fragment coords
    const int m0 = blockIdx.x * 128;

    // gmem load mapping
    const int ar = tid & 127;                     // A row within tile
    const int ak4 = (tid >> 7) << 2;              // A k sub-offset (0 or 4)
    const int br = tid >> 5;                      // B k row (0..7)
    const int bc = (lane) << 2;                   // B col (float4)

    float acc[4][4][4];
#pragma unroll
    for (int mt = 0; mt < 4; mt++)
#pragma unroll
        for (int nt = 0; nt < 4; nt++)
#pragma unroll
            for (int e = 0; e < 4; e++) acc[mt][nt][e] = 0.f;

    const int NIT = K >> 3;
    const int arow = m0 + ar;

    // prologue: load k-slab 0
    float4 av = make_float4(0.f, 0.f, 0.f, 0.f);
    if (arow < M) av = *reinterpret_cast<const float4*>(&A[(size_t)arow * K + ak4]);
    float4 bv = *reinterpret_cast<const float4*>(&B[(size_t)br * 128 + bc]);
    {
#pragma unroll
        for (int e = 0; e < 4; e++) {
            float x = (&av.x)[e];
            float h = tf32_rna(x);
            Ah[0][ak4 + e][ar] = h; Al[0][ak4 + e][ar] = x - h;
        }
        float4 bh, blo;
#pragma unroll
        for (int e = 0; e < 4; e++) {
            float x = (&bv.x)[e];
            float h = tf32_rna(x);
            (&bh.x)[e] = h; (&blo.x)[e] = x - h;
        }
        *reinterpret_cast<float4*>(&Bh[0][br][bc]) = bh;
        *reinterpret_cast<float4*>(&Bl[0][br][bc]) = blo;
    }
    __syncthreads();

    int s = 0;
    for (int it = 0; it < NIT; it++) {
        float4 av2, bv2;
        const bool more = (it + 1 < NIT);
        if (more) {
            int k0 = (it + 1) << 3;
            av2 = make_float4(0.f, 0.f, 0.f, 0.f);
            if (arow < M) av2 = *reinterpret_cast<const float4*>(&A[(size_t)arow * K + k0 + ak4]);
            bv2 = *reinterpret_cast<const float4*>(&B[(size_t)(k0 + br) * 128 + bc]);
        }

        // ---- compute on stage s ----
        float a[4][4];
#pragma unroll
        for (int mt = 0; mt < 4; mt++) {            // A_hi fragments
            int r = wm * 64 + mt * 16 + gr;
            a[mt][0] = Ah[s][gk][r];     a[mt][1] = Ah[s][gk][r + 8];
            a[mt][2] = Ah[s][gk + 4][r]; a[mt][3] = Ah[s][gk + 4][r + 8];
        }
#pragma unroll
        for (int nt = 0; nt < 4; nt++) {            // pass 1: hi*hi
            int c = wn * 32 + nt * 8 + gr;
            float b0 = Bh[s][gk][c], b1 = Bh[s][gk + 4][c];
#pragma unroll
            for (int mt = 0; mt < 4; mt++) mma_tf32(acc[mt][nt], a[mt], b0, b1);
        }
#pragma unroll
        for (int nt = 0; nt < 4; nt++) {            // pass 2: hi*lo
            int c = wn * 32 + nt * 8 + gr;
            float b0 = Bl[s][gk][c], b1 = Bl[s][gk + 4][c];
#pragma unroll
            for (int mt = 0; mt < 4; mt++) mma_tf32(acc[mt][nt], a[mt], b0, b1);
        }
#pragma unroll
        for (int mt = 0; mt < 4; mt++) {            // A_lo fragments (reuse regs)
            int r = wm * 64 + mt * 16 + gr;
            a[mt][0] = Al[s][gk][r];     a[mt][1] = Al[s][gk][r + 8];
            a[mt][2] = Al[s][gk + 4][r]; a[mt][3] = Al[s][gk + 4][r + 8];
        }
#pragma unroll
        for (int nt = 0; nt < 4; nt++) {            // pass 3: lo*hi
            int c = wn * 32 + nt * 8 + gr;
            float b0 = Bh[s][gk][c], b1 = Bh[s][gk + 4][c];
#pragma unroll
            for (int mt = 0; mt < 4; mt++) mma_tf32(acc[mt][nt], a[mt], b0, b1);
        }

        // ---- stage next slab ----
        if (more) {
            int d = s ^ 1;
#pragma unroll
            for (int e = 0; e < 4; e++) {
                float x = (&av2.x)[e];
                float h = tf32_rna(x);
                Ah[d][ak4 + e][ar] = h; Al[d][ak4 + e][ar] = x - h;
            }
            float4 bh, blo;
#pragma unroll
            for (int e = 0; e < 4; e++) {
                float x = (&bv2.x)[e];
                float h = tf32_rna(x);
                (&bh.x)[e] = h; (&blo.x)[e] = x - h;
            }
            *reinterpret_cast<float4*>(&Bh[d][br][bc]) = bh;
            *reinterpret_cast<float4*>(&Bl[d][br][bc]) = blo;
        }
        __syncthreads();
        s ^= 1;
    }

    // ---- epilogue ----
#pragma unroll
    for (int mt = 0; mt < 4; mt++) {
        int row0 = m0 + wm * 64 + mt * 16 + gr;
        int row1 = row0 + 8;
#pragma unroll
        for (int nt = 0; nt < 4; nt++) {
            int col = wn * 32 + nt * 8 + gk * 2;
            if (row0 < M)
                *reinterpret_cast<float2*>(&C[(size_t)row0 * 128 + col]) =
                    make_float2(acc[mt][nt][0], acc[mt][nt][1]);
            if (row1 < M)
                *reinterpret_cast<float2*>(&C[(size_t)row1 * 128 + col]) =
                    make_float2(acc[mt][nt][2], acc[mt][nt][3]);
        }
    }
}

// ---------------- CSR build ----------------
__global__ void zero_kernel(int rel) {
    int i = blockIdx.x * blockDim.x + threadIdx.x;
    if (i < NN) { g_deg[rel][i] = 0; g_cur[rel][i] = 0; }
}
__global__ void count_kernel(const int* __restrict__ ei, int Etot, int rel) {
    int i = blockIdx.x * blockDim.x + threadIdx.x;
    if (i >= Etot) return;
    int d = (i < EE) ? ei[EE + i] : (i - EE);   // idx >= EE: self loop
    atomicAdd(&g_deg[rel][d], 1);
}
__global__ void scan1_kernel(int rel) {
    __shared__ int s[1024];
    int tid = threadIdx.x;
    int i = blockIdx.x * 1024 + tid;
    int v = (i < NN) ? g_deg[rel][i] : 0;
    s[tid] = v; __syncthreads();
    for (int d = 1; d < 1024; d <<= 1) {
        int t = (tid >= d) ? s[tid - d] : 0;
        __syncthreads();
        s[tid] += t; __syncthreads();
    }
    if (i < NN) g_off[rel][i] = s[tid] - v;     // exclusive
    if (tid == 1023) g_part[rel][blockIdx.x] = s[1023];
}
__global__ void scan2_kernel(int rel, int P) {
    __shared__ int s[128];
    int tid = threadIdx.x;
    int v = (tid < P) ? g_part[rel][tid] : 0;
    s[tid] = v; __syncthreads();
    for (int d = 1; d < 128; d <<= 1) {
        int t = (tid >= d) ? s[tid - d] : 0;
        __syncthreads();
        s[tid] += t; __syncthreads();
    }
    if (tid < P) g_part[rel][tid] = s[tid] - v;
    if (tid == 127) g_off[rel][NN] = s[127];
}
__global__ void scan3_kernel(int rel) {
    int i = blockIdx.x * 1024 + threadIdx.x;
    if (i < NN) g_off[rel][i] += g_part[rel][blockIdx.x];
}
__global__ void fill_kernel(const int* __restrict__ ei, int Etot, int rel) {
    int i = blockIdx.x * blockDim.x + threadIdx.x;
    if (i >= Etot) return;
    int s, d;
    if (i < EE) { s = ei[i]; d = ei[EE + i]; } else { s = d = i - EE; }
    int pos = atomicAdd(&g_cur[rel][d], 1);
    g_csr[rel][g_off[rel][d] + pos] = s;
}

// ---------------- softmax-attention aggregation: warp per dst node ----------------
__global__ void agg_kernel(int rel) {
    int node = blockIdx.x * 8 + (threadIdx.x >> 5);
    int lane = threadIdx.x & 31;
    if (node >= NN) return;
    const float* __restrict__ hsL = g_hs[rel * 2 + 0];
    const float* __restrict__ hsG = g_hs[rel * 2 + 1];
    const int* __restrict__ csr = g_csr[rel];
    int beg = g_off[rel][node], end = g_off[rel][node + 1];
    float adv = (lane < 8) ? g_adP[rel][(size_t)node * 8 + lane] : 0.f;
    int h = lane >> 3;   // head owning channels [lane*4, lane*4+4)
    float4 aL = make_float4(0.f, 0.f, 0.f, 0.f);
    float4 aG = make_float4(0.f, 0.f, 0.f, 0.f);
    float dL = 0.f, dG = 0.f;
    for (int i = beg; i < end; i++) {
        int src = csr[i];
        float as = 0.f;
        if (lane < 8) as = __ldg(&g_asP[rel][(size_t)src * 8 + lane]);
        float sum8 = as + adv;
        float sL = __shfl_sync(0xffffffffu, sum8, h);
        float sG = __shfl_sync(0xffffffffu, sum8, 4 + h);
        float eL = sL > 0.f ? sL : 0.2f * sL;   // local leaky slope
        float eG = sG > 0.f ? sG : 0.3f * sG;   // global leaky slope
        float wL = __expf(eL), wG = __expf(eG); // max-shift dropped: ratio-invariant, e bounded
        dL += wL; dG += wG;
        float4 hl = *reinterpret_cast<const float4*>(&hsL[(size_t)src * 128 + lane * 4]);
        float4 hg = *reinterpret_cast<const float4*>(&hsG[(size_t)src * 128 + lane * 4]);
        aL.x += wL * hl.x; aL.y += wL * hl.y; aL.z += wL * hl.z; aL.w += wL * hl.w;
        aG.x += wG * hg.x; aG.y += wG * hg.y; aG.z += wG * hg.z; aG.w += wG * hg.w;
    }
    float iL = 1.f / (dL + 1e-16f), iG = 1.f / (dG + 1e-16f);
    float4 oL = make_float4(aL.x * iL, aL.y * iL, aL.z * iL, aL.w * iL);
    float4 oG = make_float4(aG.x * iG, aG.y * iG, aG.z * iG, aG.w * iG);
    *reinterpret_cast<float4*>(&g_agg[rel * 2 + 0][(size_t)node * 128 + lane * 4]) = oL;
    *reinterpret_cast<float4*>(&g_agg[rel * 2 + 1][(size_t)node * 128 + lane * 4]) = oG;
}

// ---------------- fuse path ----------------
__global__ void f1_user_kernel(const float* __restrict__ bl, const float* __restrict__ bg,
                               const float* __restrict__ gates) {
    size_t i = (size_t)blockIdx.x * blockDim.x + threadIdx.x;
    if (i >= (size_t)NN * 128) return;
    int c = (int)(i & 127);
    size_t n = i >> 7;
    float g0 = gates[0], g1 = gates[1];
    float m = fmaxf(g0, g1);
    float e0 = __expf(g0 - m), e1 = __expf(g1 - m);
    float inv = 1.f / (e0 + e1);
    float w0 = e0 * inv, w1 = e1 * inv;
    float loc = w0 * (g_agg[2][i] + bl[128 + c]) + w1 * (g_agg[4][i] + bl[256 + c]);
    float glb = w0 * (g_agg[3][i] + bg[128 + c]) + w1 * (g_agg[5][i] + bg[256 + c]);
    g_cat[0][n * 256 + c] = loc;
    g_cat[0][n * 256 + 128 + c] = glb;
}
__global__ void f1_item_kernel(const float* __restrict__ bl, const float* __restrict__ bg) {
    size_t i = (size_t)blockIdx.x * blockDim.x + threadIdx.x;
    if (i >= (size_t)NN * 128) return;
    int c = (int)(i & 127);
    size_t n = i >> 7;
    float loc = g_agg[0][i] + bl[c];
    float glb = g_agg[1][i] + bg[c];
    g_cat[1][n * 256 + c] = loc;
    g_cat[1][n * 256 + 128 + c] = glb;
}
__global__ void f3_kernel(int t, const float* __restrict__ gb) {
    size_t i = (size_t)blockIdx.x * blockDim.x + threadIdx.x;
    if (i >= (size_t)NN * 128) return;
    int c = (int)(i & 127);
    size_t n = i >> 7;
    float x = g_gl[t][i] + gb[c];
    float s = 1.f / (1.f + __expf(-x));
    float loc = g_cat[t][n * 256 + c], glb = g_cat[t][n * 256 + 128 + c];
    g_fus[t][i] = s * loc + (1.f - s) * glb;
}

// ---------------- launch ----------------
extern "C" void kernel_launch(void* const* d_in, const int* in_sizes, int n_in,
                              void* d_out, int out_size) {
    const float* x_user = (const float*)d_in[0];
    const float* x_item = (const float*)d_in[1];
    const float* Wsl = (const float*)d_in[2];
    const float* Wdl = (const float*)d_in[3];
    const float* asl = (const float*)d_in[4];
    const float* adl = (const float*)d_in[5];
    const float* bl  = (const float*)d_in[6];
    const float* Wsg = (const float*)d_in[7];
    const float* Wdg = (const float*)d_in[8];
    const float* asg = (const float*)d_in[9];
    const float* adg = (const float*)d_in[10];
    const float* bg  = (const float*)d_in[11];
    const float* gW  = (const float*)d_in[12];
    const float* gb  = (const float*)d_in[13];
    const float* oW  = (const float*)d_in[14];
    const float* rg  = (const float*)d_in[15];
    const int* ei_buys    = (const int*)d_in[16];
    const int* ei_rev     = (const int*)d_in[17];
    const int* ei_follows = (const int*)d_in[18];
    float* out = (float*)d_out;

    float *hs_base, *cat_base, *gl_base, *fus_base;
    cudaGetSymbolAddress((void**)&hs_base, g_hs);
    cudaGetSymbolAddress((void**)&cat_base, g_cat);
    cudaGetSymbolAddress((void**)&gl_base, g_gl);
    cudaGetSymbolAddress((void**)&fus_base, g_fus);

    const int GA = (NN * 32 + 255) / 256;        // warp-per-node kernels
    const int GB = (NN + 127) / 128;             // GEMM row tiles (128)
    const int GE = (NN * 128 + 255) / 256;       // elementwise
    const int GSCAN = (NN + 1023) / 1024;        // 98

    prep_v_kernel<<<(12288 + 255) / 256, 256>>>(Wsl, Wsg, Wdl, Wdg, asl, asg, adl, adg);

    // attention logits (src/dst per relation)
    compute_a_kernel<<<GA, 256>>>(x_user, 0, 0);
    compute_a_kernel<<<GA, 256>>>(x_item, 0, 1);
    compute_a_kernel<<<GA, 256>>>(x_item, 1, 0);
    compute_a_kernel<<<GA, 256>>>(x_user, 1, 1);
    compute_a_kernel<<<GA, 256>>>(x_user, 2, 0);
    compute_a_kernel<<<GA, 256>>>(x_user, 2, 1);

    // src projections hs (6 GEMMs, tf32 tensor cores)
    gemm_tf32_kernel<<<GB, 256>>>(x_user, Wsl + 0 * 16384, hs_base + (size_t)0 * NN * 128, NN, 128);
    gemm_tf32_kernel<<<GB, 256>>>(x_user, Wsg + 0 * 16384, hs_base + (size_t)1 * NN * 128, NN, 128);
    gemm_tf32_kernel<<<GB, 256>>>(x_item, Wsl + 1 * 16384, hs_base + (size_t)2 * NN * 128, NN, 128);
    gemm_tf32_kernel<<<GB, 256>>>(x_item, Wsg + 1 * 16384, hs_base + (size_t)3 * NN * 128, NN, 128);
    gemm_tf32_kernel<<<GB, 256>>>(x_user, Wsl + 2 * 16384, hs_base + (size_t)4 * NN * 128, NN, 128);
    gemm_tf32_kernel<<<GB, 256>>>(x_user, Wsg + 2 * 16384, hs_base + (size_t)5 * NN * 128, NN, 128);

    // per-relation CSR build + aggregation
    const int* eis[3] = {ei_buys, ei_rev, ei_follows};
    const int etot[3] = {EE, EE, EE + NN};
    for (int r = 0; r < 3; r++) {
        int Et = etot[r];
        zero_kernel<<<(NN + 255) / 256, 256>>>(r);
        count_kernel<<<(Et + 255) / 256, 256>>>(eis[r], Et, r);
        scan1_kernel<<<GSCAN, 1024>>>(r);
        scan2_kernel<<<1, 128>>>(r, GSCAN);
        scan3_kernel<<<GSCAN, 1024>>>(r);
        fill_kernel<<<(Et + 255) / 256, 256>>>(eis[r], Et, r);
        agg_kernel<<<(NN + 7) / 8, 256>>>(r);
    }

    // fuse
    f1_user_kernel<<<GE, 256>>>(bl, bg, rg);
    f1_item_kernel<<<GE, 256>>>(bl, bg);
    gemm_tf32_kernel<<<GB, 256>>>(cat_base + (size_t)0 * NN * 256, gW + 0 * 32768,
                                  gl_base + (size_t)0 * NN * 128, NN, 256);
    gemm_tf32_kernel<<<GB, 256>>>(cat_base + (size_t)1 * NN * 256, gW + 1 * 32768,
                                  gl_base + (size_t)1 * NN * 128, NN, 256);
    f3_kernel<<<GE, 256>>>(0, gb);
    f3_kernel<<<GE, 256>>>(1, gb + 128);
    gemm_tf32_kernel<<<GB, 256>>>(fus_base + (size_t)0 * NN * 128, oW + 0 * 16384, out, NN, 128);
    gemm_tf32_kernel<<<GB, 256>>>(fus_base + (size_t)1 * NN * 128, oW + 1 * 16384,
                                  out + (size_t)NN * 128, NN, 128);
}

// round 4
// speedup vs baseline: 1.4648x; 1.0776x over previous
#include <cuda_runtime.h>
#include <cstdint>

#define NN 100000
#define EE 1000000

// ---------------- scratch (__device__ globals; no allocation allowed) ----------------
__device__ float g_hs[6][NN * 128];     // projected src features per (rel, scale)
__device__ float g_agg[6][NN * 128];    // normalized aggregation per (rel, scale)
__device__ float g_asP[3][NN * 8];      // a_src packed [node][local h0..3, global h0..3]
__device__ float g_adP[3][NN * 8];      // a_dst packed
__device__ float g_vpack[3 * 2 * 8 * 128]; // folded W_dst·att_dst vectors
__device__ int   g_deg[3][NN];
__device__ int   g_cur[3][NN];
__device__ int   g_off[3][NN + 1];
__device__ int   g_part[3][256];
__device__ int   g_csr[3][EE + NN];
__device__ float g_fus[2][NN * 128];    // fused features

// ---------------- helpers ----------------
__device__ __forceinline__ float tf32_rna(float x) {
    uint32_t u;
    asm("cvt.rna.tf32.f32 %0, %1;" : "=r"(u) : "f"(x));
    return __uint_as_float(u);
}

__device__ __forceinline__ void mma_tf32(float* d, const float* a, float b0, float b1) {
    asm volatile(
        "mma.sync.aligned.m16n8k8.row.col.f32.tf32.tf32.f32 "
        "{%0,%1,%2,%3}, {%4,%5,%6,%7}, {%8,%9}, {%0,%1,%2,%3};"
        : "+f"(d[0]), "+f"(d[1]), "+f"(d[2]), "+f"(d[3])
        : "r"(__float_as_uint(a[0])), "r"(__float_as_uint(a[1])),
          "r"(__float_as_uint(a[2])), "r"(__float_as_uint(a[3])),
          "r"(__float_as_uint(b0)), "r"(__float_as_uint(b1)));
}

// ---------------- fold W_dst·att_dst (dst side only) ----------------
__global__ void prep_v_kernel(const float* __restrict__ Wdl, const float* __restrict__ Wdg,
                              const float* __restrict__ adl, const float* __restrict__ adg) {
    int idx = blockIdx.x * blockDim.x + threadIdx.x;
    if (idx >= 3 * 2 * 128 * 4) return;
    int h = idx & 3, k = (idx >> 2) & 127, sc = (idx >> 9) & 1, rel = idx >> 10;
    const float* W = (sc ? Wdg : Wdl) + (size_t)rel * 128 * 128;
    const float* att = (sc ? adg : adl) + rel * 4 * 32;
    float s = 0.f;
#pragma unroll
    for (int c = 0; c < 32; c++) s += W[k * 128 + h * 32 + c] * att[h * 32 + c];
    g_vpack[((rel * 2 + 1) * 8 + sc * 4 + h) * 128 + k] = s;
}

// ---------------- a_dst = x_d @ v  (warp per node) ----------------
__global__ void compute_a_kernel(const float* __restrict__ x, int rel) {
    int node = (blockIdx.x * blockDim.x + threadIdx.x) >> 5;
    int lane = threadIdx.x & 31;
    if (node >= NN) return;
    const float* vp = &g_vpack[(size_t)(rel * 2 + 1) * 8 * 128];
    float4 x4 = *reinterpret_cast<const float4*>(&x[(size_t)node * 128 + lane * 4]);
    float p[8];
#pragma unroll
    for (int j = 0; j < 8; j++) {
        float4 v4 = *reinterpret_cast<const float4*>(&vp[j * 128 + lane * 4]);
        p[j] = x4.x * v4.x + x4.y * v4.y + x4.z * v4.z + x4.w * v4.w;
    }
#pragma unroll
    for (int d = 16; d > 0; d >>= 1)
#pragma unroll
        for (int j = 0; j < 8; j++) p[j] += __shfl_xor_sync(0xffffffffu, p[j], d);
    if (lane < 8) g_adP[rel][(size_t)node * 8 + lane] = p[lane];
}

// ---------------- tf32 tensor-core GEMM (3xTF32): C[M,128] = A[M,K] @ B[K,128] ----------------
// CTA tile 128x128, BK=8, 8 warps of 64x32, double-buffered smem.
// Optional epilogue: a_s[row, head=wn] = sum_c acc[row, wn*32+c] * attp[wn*32+c]
__global__ __launch_bounds__(256) void gemm_tf32_kernel(const float* __restrict__ A,
                                                        const float* __restrict__ B,
                                                        float* __restrict__ C, int M, int K,
                                                        const float* __restrict__ attp,
                                                        float* __restrict__ asP_out, int slot) {
    __shared__ float Ah[2][8][136], Al[2][8][136];
    __shared__ float Bh[2][8][136], Bl[2][8][136];
    const int tid = threadIdx.x;
    const int lane = tid & 31, warp = tid >> 5;
    const int wm = warp >> 2, wn = warp & 3;
    const int gr = lane >> 2, gk = lane & 3;
    const int m0 = blockIdx.x * 128;

    const int ar = tid & 127;
    const int ak4 = (tid >> 7) << 2;
    const int br = tid >> 5;
    const int bc = lane << 2;

    float acc[4][4][4];
#pragma unroll
    for (int mt = 0; mt < 4; mt++)
#pragma unroll
        for (int nt = 0; nt < 4; nt++)
#pragma unroll
            for (int e = 0; e < 4; e++) acc[mt][nt][e] = 0.f;

    const int NIT = K >> 3;
    const int arow = m0 + ar;

    float4 av = make_float4(0.f, 0.f, 0.f, 0.f);
    if (arow < M) av = *reinterpret_cast<const float4*>(&A[(size_t)arow * K + ak4]);
    float4 bv = *reinterpret_cast<const float4*>(&B[(size_t)br * 128 + bc]);
    {
#pragma unroll
        for (int e = 0; e < 4; e++) {
            float x = (&av.x)[e];
            float h = tf32_rna(x);
            Ah[0][ak4 + e][ar] = h; Al[0][ak4 + e][ar] = x - h;
        }
        float4 bh, blo;
#pragma unroll
        for (int e = 0; e < 4; e++) {
            float x = (&bv.x)[e];
            float h = tf32_rna(x);
            (&bh.x)[e] = h; (&blo.x)[e] = x - h;
        }
        *reinterpret_cast<float4*>(&Bh[0][br][bc]) = bh;
        *reinterpret_cast<float4*>(&Bl[0][br][bc]) = blo;
    }
    __syncthreads();

    int s = 0;
    for (int it = 0; it < NIT; it++) {
        float4 av2, bv2;
        const bool more = (it + 1 < NIT);
        if (more) {
            int k0 = (it + 1) << 3;
            av2 = make_float4(0.f, 0.f, 0.f, 0.f);
            if (arow < M) av2 = *reinterpret_cast<const float4*>(&A[(size_t)arow * K + k0 + ak4]);
            bv2 = *reinterpret_cast<const float4*>(&B[(size_t)(k0 + br) * 128 + bc]);
        }

        float a[4][4];
#pragma unroll
        for (int mt = 0; mt < 4; mt++) {
            int r = wm * 64 + mt * 16 + gr;
            a[mt][0] = Ah[s][gk][r];     a[mt][1] = Ah[s][gk][r + 8];
            a[mt][2] = Ah[s][gk + 4][r]; a[mt][3] = Ah[s][gk + 4][r + 8];
        }
#pragma unroll
        for (int nt = 0; nt < 4; nt++) {
            int c = wn * 32 + nt * 8 + gr;
            float b0 = Bh[s][gk][c], b1 = Bh[s][gk + 4][c];
#pragma unroll
            for (int mt = 0; mt < 4; mt++) mma_tf32(acc[mt][nt], a[mt], b0, b1);
        }
#pragma unroll
        for (int nt = 0; nt < 4; nt++) {
            int c = wn * 32 + nt * 8 + gr;
            float b0 = Bl[s][gk][c], b1 = Bl[s][gk + 4][c];
#pragma unroll
            for (int mt = 0; mt < 4; mt++) mma_tf32(acc[mt][nt], a[mt], b0, b1);
        }
#pragma unroll
        for (int mt = 0; mt < 4; mt++) {
            int r = wm * 64 + mt * 16 + gr;
            a[mt][0] = Al[s][gk][r];     a[mt][1] = Al[s][gk][r + 8];
            a[mt][2] = Al[s][gk + 4][r]; a[mt][3] = Al[s][gk + 4][r + 8];
        }
#pragma unroll
        for (int nt = 0; nt < 4; nt++) {
            int c = wn * 32 + nt * 8 + gr;
            float b0 = Bh[s][gk][c], b1 = Bh[s][gk + 4][c];
#pragma unroll
            for (int mt = 0; mt < 4; mt++) mma_tf32(acc[mt][nt], a[mt], b0, b1);
        }

        if (more) {
            int d = s ^ 1;
#pragma unroll
            for (int e = 0; e < 4; e++) {
                float x = (&av2.x)[e];
                float h = tf32_rna(x);
                Ah[d][ak4 + e][ar] = h; Al[d][ak4 + e][ar] = x - h;
            }
            float4 bh, blo;
#pragma unroll
            for (int e = 0; e < 4; e++) {
                float x = (&bv2.x)[e];
                float h = tf32_rna(x);
                (&bh.x)[e] = h; (&blo.x)[e] = x - h;
            }
            *reinterpret_cast<float4*>(&Bh[d][br][bc]) = bh;
            *reinterpret_cast<float4*>(&Bl[d][br][bc]) = blo;
        }
        __syncthreads();
        s ^= 1;
    }

    // ---- epilogue: store C ----
#pragma unroll
    for (int mt = 0; mt < 4; mt++) {
        int row0 = m0 + wm * 64 + mt * 16 + gr;
        int row1 = row0 + 8;
#pragma unroll
        for (int nt = 0; nt < 4; nt++) {
            int col = wn * 32 + nt * 8 + gk * 2;
            if (row0 < M)
                *reinterpret_cast<float2*>(&C[(size_t)row0 * 128 + col]) =
                    make_float2(acc[mt][nt][0], acc[mt][nt][1]);
            if (row1 < M)
                *reinterpret_cast<float2*>(&C[(size_t)row1 * 128 + col]) =
                    make_float2(acc[mt][nt][2], acc[mt][nt][3]);
        }
    }

    // ---- fused a_src epilogue: head wn == warp wn's 32-col range ----
    if (attp) {
        float attv[4][2];
#pragma unroll
        for (int nt = 0; nt < 4; nt++) {
            attv[nt][0] = attp[wn * 32 + nt * 8 + gk * 2];
            attv[nt][1] = attp[wn * 32 + nt * 8 + gk * 2 + 1];
        }
#pragma unroll
        for (int mt = 0; mt < 4; mt++) {
            float s0 = 0.f, s1 = 0.f;
#pragma unroll
            for (int nt = 0; nt < 4; nt++) {
                s0 += acc[mt][nt][0] * attv[nt][0] + acc[mt][nt][1] * attv[nt][1];
                s1 += acc[mt][nt][2] * attv[nt][0] + acc[mt][nt][3] * attv[nt][1];
            }
            s0 += __shfl_xor_sync(0xffffffffu, s0, 1);
            s0 += __shfl_xor_sync(0xffffffffu, s0, 2);
            s1 += __shfl_xor_sync(0xffffffffu, s1, 1);
            s1 += __shfl_xor_sync(0xffffffffu, s1, 2);
            if (gk == 0) {
                int row0 = m0 + wm * 64 + mt * 16 + gr;
                if (row0 < M) asP_out[(size_t)row0 * 8 + slot + wn] = s0;
                if (row0 + 8 < M) asP_out[(size_t)(row0 + 8) * 8 + slot + wn] = s1;
            }
        }
    }
}

// ---------------- fused gate GEMM: builds cat on the fly, applies sigmoid gate ----------------
// t=0: user (agg2/agg4 loc, agg3/agg5 glb, rel-softmax weights), t=1: item (agg0/agg1)
__global__ __launch_bounds__(256) void gatefuse_kernel(int t,
                                                       const float* __restrict__ bl,
                                                       const float* __restrict__ bg,
                                                       const float* __restrict__ rg,
                                                       const float* __restrict__ gW,
                                                       const float* __restrict__ gb) {
    __shared__ float Ah[2][8][136], Al[2][8][136];
    __shared__ float Bh[2][8][136], Bl[2][8][136];
    const int tid = threadIdx.x;
    const int lane = tid & 31, warp = tid >> 5;
    const int wm = warp >> 2, wn = warp & 3;
    const int gr = lane >> 2, gk = lane & 3;
    const int m0 = blockIdx.x * 128;
    const int K = 256;

    float w0 = 1.f, w1 = 0.f;
    if (t == 0) {
        float r0 = rg[0], r1 = rg[1];
        float m = fmaxf(r0, r1);
        float e0 = __expf(r0 - m), e1 = __expf(r1 - m);
        float inv = 1.f / (e0 + e1);
        w0 = e0 * inv; w1 = e1 * inv;
    }
    const float* B = gW + (size_t)t * 32768;
    const float* gbt = gb + t * 128;
    float* fus = &g_fus[t][0];

    const int ar = tid & 127;
    const int ak4 = (tid >> 7) << 2;
    const int br = tid >> 5;
    const int bc = lane << 2;
    const int arow = m0 + ar;

    // A-row builder: cat[row, cc..cc+3] (cc block never straddles 128)
    auto loadA = [&](int cc) -> float4 {
        float4 v = make_float4(0.f, 0.f, 0.f, 0.f);
        if (arow >= NN) return v;
        if (cc < 128) {
            if (t == 0) {
                float4 a2 = *reinterpret_cast<const float4*>(&g_agg[2][(size_t)arow * 128 + cc]);
                float4 a4 = *reinterpret_cast<const float4*>(&g_agg[4][(size_t)arow * 128 + cc]);
                float4 b1 = *reinterpret_cast<const float4*>(&bl[128 + cc]);
                float4 b2 = *reinterpret_cast<const float4*>(&bl[256 + cc]);
#pragma unroll
                for (int e = 0; e < 4; e++)
                    (&v.x)[e] = w0 * ((&a2.x)[e] + (&b1.x)[e]) + w1 * ((&a4.x)[e] + (&b2.x)[e]);
            } else {
                float4 a0 = *reinterpret_cast<const float4*>(&g_agg[0][(size_t)arow * 128 + cc]);
                float4 b0 = *reinterpret_cast<const float4*>(&bl[cc]);
#pragma unroll
                for (int e = 0; e < 4; e++) (&v.x)[e] = (&a0.x)[e] + (&b0.x)[e];
            }
        } else {
            int c = cc - 128;
            if (t == 0) {
                float4 a3 = *reinterpret_cast<const float4*>(&g_agg[3][(size_t)arow * 128 + c]);
                float4 a5 = *reinterpret_cast<const float4*>(&g_agg[5][(size_t)arow * 128 + c]);
                float4 b1 = *reinterpret_cast<const float4*>(&bg[128 + c]);
                float4 b2 = *reinterpret_cast<const float4*>(&bg[256 + c]);
#pragma unroll
                for (int e = 0; e < 4; e++)
                    (&v.x)[e] = w0 * ((&a3.x)[e] + (&b1.x)[e]) + w1 * ((&a5.x)[e] + (&b2.x)[e]);
            } else {
                float4 a1 = *reinterpret_cast<const float4*>(&g_agg[1][(size_t)arow * 128 + c]);
                float4 b0 = *reinterpret_cast<const float4*>(&bg[c]);
#pragma unroll
                for (int e = 0; e < 4; e++) (&v.x)[e] = (&a1.x)[e] + (&b0.x)[e];
            }
        }
        return v;
    };

    float acc[4][4][4];
#pragma unroll
    for (int mt = 0; mt < 4; mt++)
#pragma unroll
        for (int nt = 0; nt < 4; nt++)
#pragma unroll
            for (int e = 0; e < 4; e++) acc[mt][nt][e] = 0.f;

    const int NIT = K >> 3;

    float4 av = loadA(ak4);
    float4 bv = *reinterpret_cast<const float4*>(&B[(size_t)br * 128 + bc]);
    {
#pragma unroll
        for (int e = 0; e < 4; e++) {
            float x = (&av.x)[e];
            float h = tf32_rna(x);
            Ah[0][ak4 + e][ar] = h; Al[0][ak4 + e][ar] = x - h;
        }
        float4 bh, blo;
#pragma unroll
        for (int e = 0; e < 4; e++) {
            float x = (&bv.x)[e];
            float h = tf32_rna(x);
            (&bh.x)[e] = h; (&blo.x)[e] = x - h;
        }
        *reinterpret_cast<float4*>(&Bh[0][br][bc]) = bh;
        *reinterpret_cast<float4*>(&Bl[0][br][bc]) = blo;
    }
    __syncthreads();

    int s = 0;
    for (int it = 0; it < NIT; it++) {
        float4 av2, bv2;
        const bool more = (it + 1 < NIT);
        if (more) {
            int k0 = (it + 1) << 3;
            av2 = loadA(k0 + ak4);
            bv2 = *reinterpret_cast<const float4*>(&B[(size_t)(k0 + br) * 128 + bc]);
        }
        float a[4][4];
#pragma unroll
        for (int mt = 0; mt < 4; mt++) {
            int r = wm * 64 + mt * 16 + gr;
            a[mt][0] = Ah[s][gk][r];     a[mt][1] = Ah[s][gk][r + 8];
            a[mt][2] = Ah[s][gk + 4][r]; a[mt][3] = Ah[s][gk + 4][r + 8];
        }
#pragma unroll
        for (int nt = 0; nt < 4; nt++) {
            int c = wn * 32 + nt * 8 + gr;
            float b0 = Bh[s][gk][c], b1 = Bh[s][gk + 4][c];
#pragma unroll
            for (int mt = 0; mt < 4; mt++) mma_tf32(acc[mt][nt], a[mt], b0, b1);
        }
#pragma unroll
        for (int nt = 0; nt < 4; nt++) {
            int c = wn * 32 + nt * 8 + gr;
            float b0 = Bl[s][gk][c], b1 = Bl[s][gk + 4][c];
#pragma unroll
            for (int mt = 0; mt < 4; mt++) mma_tf32(acc[mt][nt], a[mt], b0, b1);
        }
#pragma unroll
        for (int mt = 0; mt < 4; mt++) {
            int r = wm * 64 + mt * 16 + gr;
            a[mt][0] = Al[s][gk][r];     a[mt][1] = Al[s][gk][r + 8];
            a[mt][2] = Al[s][gk + 4][r]; a[mt][3] = Al[s][gk + 4][r + 8];
        }
#pragma unroll
        for (int nt = 0; nt < 4; nt++) {
            int c = wn * 32 + nt * 8 + gr;
            float b0 = Bh[s][gk][c], b1 = Bh[s][gk + 4][c];
#pragma unroll
            for (int mt = 0; mt < 4; mt++) mma_tf32(acc[mt][nt], a[mt], b0, b1);
        }
        if (more) {
            int d = s ^ 1;
#pragma unroll
            for (int e = 0; e < 4; e++) {
                float x = (&av2.x)[e];
                float h = tf32_rna(x);
                Ah[d][ak4 + e][ar] = h; Al[d][ak4 + e][ar] = x - h;
            }
            float4 bh, blo;
#pragma unroll
            for (int e = 0; e < 4; e++) {
                float x = (&bv2.x)[e];
                float h = tf32_rna(x);
                (&bh.x)[e] = h; (&blo.x)[e] = x - h;
            }
            *reinterpret_cast<float4*>(&Bh[d][br][bc]) = bh;
            *reinterpret_cast<float4*>(&Bl[d][br][bc]) = blo;
        }
        __syncthreads();
        s ^= 1;
    }

    // epilogue: sigmoid gate, recompute loc/glb, write fus
#pragma unroll
    for (int mt = 0; mt < 4; mt++) {
#pragma unroll
        for (int half = 0; half < 2; half++) {
            int row = m0 + wm * 64 + mt * 16 + gr + half * 8;
            if (row >= NN) continue;
#pragma unroll
            for (int nt = 0; nt < 4; nt++) {
                int col = wn * 32 + nt * 8 + gk * 2;
                float gl0 = acc[mt][nt][half * 2 + 0] + gbt[col];
                float gl1 = acc[mt][nt][half * 2 + 1] + gbt[col + 1];
                float s0 = 1.f / (1.f + __expf(-gl0));
                float s1 = 1.f / (1.f + __expf(-gl1));
                float2 loc, glb;
                if (t == 0) {
                    float2 a2 = *reinterpret_cast<const float2*>(&g_agg[2][(size_t)row * 128 + col]);
                    float2 a4 = *reinterpret_cast<const float2*>(&g_agg[4][(size_t)row * 128 + col]);
                    float2 a3 = *reinterpret_cast<const float2*>(&g_agg[3][(size_t)row * 128 + col]);
                    float2 a5 = *reinterpret_cast<const float2*>(&g_agg[5][(size_t)row * 128 + col]);
                    loc.x = w0 * (a2.x + bl[128 + col]) + w1 * (a4.x + bl[256 + col]);
                    loc.y = w0 * (a2.y + bl[128 + col + 1]) + w1 * (a4.y + bl[256 + col + 1]);
                    glb.x = w0 * (a3.x + bg[128 + col]) + w1 * (a5.x + bg[256 + col]);
                    glb.y = w0 * (a3.y + bg[128 + col + 1]) + w1 * (a5.y + bg[256 + col + 1]);
                } else {
                    float2 a0 = *reinterpret_cast<const float2*>(&g_agg[0][(size_t)row * 128 + col]);
                    float2 a1 = *reinterpret_cast<const float2*>(&g_agg[1][(size_t)row * 128 + col]);
                    loc.x = a0.x + bl[col];     loc.y = a0.y + bl[col + 1];
                    glb.x = a1.x + bg[col];     glb.y = a1.y + bg[col + 1];
                }
                float2 o;
                o.x = s0 * loc.x + (1.f - s0) * glb.x;
                o.y = s1 * loc.y + (1.f - s1) * glb.y;
                *reinterpret_cast<float2*>(&fus[(size_t)row * 128 + col]) = o;
            }
        }
    }
}

// ---------------- merged CSR build (all 3 relations) ----------------
#define ETOT (3 * EE + NN)
__global__ void zero_all_kernel() {
    int i = blockIdx.x * blockDim.x + threadIdx.x;
    if (i < 3 * NN) { (&g_deg[0][0])[i] = 0; (&g_cur[0][0])[i] = 0; }
}
__device__ __forceinline__ void edge_decode(int i, const int* eb, const int* er, const int* ef,
                                            int& rel, int& s, int& d) {
    if (i < EE) { rel = 0; s = eb[i]; d = eb[EE + i]; }
    else if (i < 2 * EE) { rel = 1; int j = i - EE; s = er[j]; d = er[EE + j]; }
    else { int j = i - 2 * EE; rel = 2;
           if (j < EE) { s = ef[j]; d = ef[EE + j]; } else { s = d = j - EE; } }
}
__global__ void count_all_kernel(const int* __restrict__ eb, const int* __restrict__ er,
                                 const int* __restrict__ ef) {
    int i = blockIdx.x * blockDim.x + threadIdx.x;
    if (i >= ETOT) return;
    int rel, s, d; edge_decode(i, eb, er, ef, rel, s, d);
    atomicAdd(&g_deg[rel][d], 1);
}
#define GSCAN ((NN + 1023) / 1024)
__global__ void scan1_all_kernel() {
    __shared__ int s[1024];
    int rel = blockIdx.x / GSCAN, blk = blockIdx.x % GSCAN;
    int tid = threadIdx.x;
    int i = blk * 1024 + tid;
    int v = (i < NN) ? g_deg[rel][i] : 0;
    s[tid] = v; __syncthreads();
    for (int d = 1; d < 1024; d <<= 1) {
        int t = (tid >= d) ? s[tid - d] : 0;
        __syncthreads();
        s[tid] += t; __syncthreads();
    }
    if (i < NN) g_off[rel][i] = s[tid] - v;
    if (tid == 1023) g_part[rel][blk] = s[1023];
}
__global__ void scan2_all_kernel() {
    __shared__ int s[128];
    int rel = blockIdx.x;
    int tid = threadIdx.x;
    int v = (tid < GSCAN) ? g_part[rel][tid] : 0;
    s[tid] = v; __syncthreads();
    for (int d = 1; d < 128; d <<= 1) {
        int t = (tid >= d) ? s[tid - d] : 0;
        __syncthreads();
        s[tid] += t; __syncthreads();
    }
    if (tid < GSCAN) g_part[rel][tid] = s[tid] - v;
    if (tid == 127) g_off[rel][NN] = s[127];
}
__global__ void scan3_all_kernel() {
    int rel = blockIdx.x / GSCAN, blk = blockIdx.x % GSCAN;
    int i = blk * 1024 + threadIdx.x;
    if (i < NN) g_off[rel][i] += g_part[rel][blk];
}
__global__ void fill_all_kernel(const int* __restrict__ eb, const int* __restrict__ er,
                                const int* __restrict__ ef) {
    int i = blockIdx.x * blockDim.x + threadIdx.x;
    if (i >= ETOT) return;
    int rel, s, d; edge_decode(i, eb, er, ef, rel, s, d);
    int pos = atomicAdd(&g_cur[rel][d], 1);
    g_csr[rel][g_off[rel][d] + pos] = s;
}

// ---------------- softmax-attention aggregation: warp per dst node, one scale ----------------
__global__ void agg_kernel(int rel, int sc, float slope) {
    int node = blockIdx.x * 8 + (threadIdx.x >> 5);
    int lane = threadIdx.x & 31;
    if (node >= NN) return;
    const float* __restrict__ hsv = g_hs[rel * 2 + sc];
    const int* __restrict__ csr = g_csr[rel];
    int beg = g_off[rel][node], end = g_off[rel][node + 1];
    float adv = (lane < 4) ? g_adP[rel][(size_t)node * 8 + sc * 4 + lane] : 0.f;
    int h = lane >> 3;
    float4 a = make_float4(0.f, 0.f, 0.f, 0.f);
    float den = 0.f;
    for (int i = beg; i < end; i++) {
        int src = csr[i];
        float as = (lane < 4) ? __ldg(&g_asP[rel][(size_t)src * 8 + sc * 4 + lane]) : 0.f;
        float sum = as + adv;
        float sv = __shfl_sync(0xffffffffu, sum, h);
        float e = sv > 0.f ? sv : slope * sv;
        float w = __expf(e);
        den += w;
        float4 hv = *reinterpret_cast<const float4*>(&hsv[(size_t)src * 128 + lane * 4]);
        a.x += w * hv.x; a.y += w * hv.y; a.z += w * hv.z; a.w += w * hv.w;
    }
    float inv = 1.f / (den + 1e-16f);
    float4 o = make_float4(a.x * inv, a.y * inv, a.z * inv, a.w * inv);
    *reinterpret_cast<float4*>(&g_agg[rel * 2 + sc][(size_t)node * 128 + lane * 4]) = o;
}

// ---------------- launch ----------------
extern "C" void kernel_launch(void* const* d_in, const int* in_sizes, int n_in,
                              void* d_out, int out_size) {
    const float* x_user = (const float*)d_in[0];
    const float* x_item = (const float*)d_in[1];
    const float* Wsl = (const float*)d_in[2];
    const float* Wdl = (const float*)d_in[3];
    const float* asl = (const float*)d_in[4];
    const float* adl = (const float*)d_in[5];
    const float* bl  = (const float*)d_in[6];
    const float* Wsg = (const float*)d_in[7];
    const float* Wdg = (const float*)d_in[8];
    const float* asg = (const float*)d_in[9];
    const float* adg = (const float*)d_in[10];
    const float* bg  = (const float*)d_in[11];
    const float* gW  = (const float*)d_in[12];
    const float* gb  = (const float*)d_in[13];
    const float* oW  = (const float*)d_in[14];
    const float* rg  = (const float*)d_in[15];
    const int* ei_buys    = (const int*)d_in[16];
    const int* ei_rev     = (const int*)d_in[17];
    const int* ei_follows = (const int*)d_in[18];
    float* out = (float*)d_out;

    float *hs_base, *asP_base, *fus_base;
    cudaGetSymbolAddress((void**)&hs_base, g_hs);
    cudaGetSymbolAddress((void**)&asP_base, g_asP);
    cudaGetSymbolAddress((void**)&fus_base, g_fus);

    const int GA = (NN * 32 + 255) / 256;
    const int GB = (NN + 127) / 128;

    prep_v_kernel<<<(3072 + 255) / 256, 256>>>(Wdl, Wdg, adl, adg);

    // dst-side attention logits
    compute_a_kernel<<<GA, 256>>>(x_item, 0);
    compute_a_kernel<<<GA, 256>>>(x_user, 1);
    compute_a_kernel<<<GA, 256>>>(x_user, 2);

    // CSR build (merged, overlaps nothing but is independent of GEMMs)
    zero_all_kernel<<<(3 * NN + 255) / 256, 256>>>();
    count_all_kernel<<<(ETOT + 255) / 256, 256>>>(ei_buys, ei_rev, ei_follows);
    scan1_all_kernel<<<3 * GSCAN, 1024>>>();
    scan2_all_kernel<<<3, 128>>>();
    scan3_all_kernel<<<3 * GSCAN, 1024>>>();
    fill_all_kernel<<<(ETOT + 255) / 256, 256>>>(ei_buys, ei_rev, ei_follows);

    // src projections hs (6 GEMMs) with fused a_src epilogue
    gemm_tf32_kernel<<<GB, 256>>>(x_user, Wsl + 0 * 16384, hs_base + (size_t)0 * NN * 128, NN, 128,
                                  asl + 0 * 128, asP_base + (size_t)0 * NN * 8, 0);
    gemm_tf32_kernel<<<GB, 256>>>(x_user, Wsg + 0 * 16384, hs_base + (size_t)1 * NN * 128, NN, 128,
                                  asg + 0 * 128, asP_base + (size_t)0 * NN * 8, 4);
    gemm_tf32_kernel<<<GB, 256>>>(x_item, Wsl + 1 * 16384, hs_base + (size_t)2 * NN * 128, NN, 128,
                                  asl + 1 * 128, asP_base + (size_t)1 * NN * 8, 0);
    gemm_tf32_kernel<<<GB, 256>>>(x_item, Wsg + 1 * 16384, hs_base + (size_t)3 * NN * 128, NN, 128,
                                  asg + 1 * 128, asP_base + (size_t)1 * NN * 8, 4);
    gemm_tf32_kernel<<<GB, 256>>>(x_user, Wsl + 2 * 16384, hs_base + (size_t)4 * NN * 128, NN, 128,
                                  asl + 2 * 128, asP_base + (size_t)2 * NN * 8, 0);
    gemm_tf32_kernel<<<GB, 256>>>(x_user, Wsg + 2 * 16384, hs_base + (size_t)5 * NN * 128, NN, 128,
                                  asg + 2 * 128, asP_base + (size_t)2 * NN * 8, 4);

    // aggregation: one (relation, scale) per launch -> hs working set fits L2
    for (int r = 0; r < 3; r++) {
        agg_kernel<<<(NN + 7) / 8, 256>>>(r, 0, 0.2f);
        agg_kernel<<<(NN + 7) / 8, 256>>>(r, 1, 0.3f);
    }

    // fused gate+sigmoid+mix (replaces f1/f3 + gate GEMM)
    gatefuse_kernel<<<GB, 256>>>(0, bl, bg, rg, gW, gb);
    gatefuse_kernel<<<GB, 256>>>(1, bl, bg, rg, gW, gb);

    // output GEMMs
    gemm_tf32_kernel<<<GB, 256>>>(fus_base + (size_t)0 * NN * 128, oW + 0 * 16384, out, NN, 128,
                                  nullptr, nullptr, 0);
    gemm_tf32_kernel<<<GB, 256>>>(fus_base + (size_t)1 * NN * 128, oW + 1 * 16384,
                                  out + (size_t)NN * 128, NN, 128, nullptr, nullptr, 0);
}

// round 5
// speedup vs baseline: 1.8279x; 1.2479x over previous
#include <cuda_runtime.h>
#include <cuda_bf16.h>
#include <cstdint>

#define NN 100000
#define EE 1000000

// ---------------- scratch (__device__ globals; no allocation allowed) ----------------
__device__ float g_hs[6][NN * 128];     // projected src features per (rel, scale)
__device__ float g_agg[6][NN * 128];    // normalized aggregation per (rel, scale)
__device__ float g_asP[3][NN * 8];      // a_src packed [node][local h0..3, global h0..3]
__device__ float g_adP[3][NN * 8];      // a_dst packed
__device__ float g_vpack[3 * 2 * 8 * 128]; // folded W_dst·att_dst vectors
__device__ int   g_deg[3][NN];
__device__ int   g_cur[3][NN];
__device__ int   g_off[3][NN + 1];
__device__ int   g_part[3][256];
__device__ int   g_csr[3][EE + NN];
__device__ float g_fus[2][NN * 128];    // fused features

// ---------------- helpers ----------------
// pack two floats to bf16x2: low half = lo arg (smaller k), high half = hi arg
__device__ __forceinline__ uint32_t packbf(float lo, float hi) {
    uint32_t r;
    asm("cvt.rn.bf16x2.f32 %0, %1, %2;" : "=r"(r) : "f"(hi), "f"(lo));
    return r;
}
__device__ __forceinline__ float bfhi(float x) {
    return __bfloat162float(__float2bfloat16_rn(x));
}

__device__ __forceinline__ void mma_bf16(float* d, const uint32_t* a, uint32_t b0, uint32_t b1) {
    asm volatile(
        "mma.sync.aligned.m16n8k16.row.col.f32.bf16.bf16.f32 "
        "{%0,%1,%2,%3}, {%4,%5,%6,%7}, {%8,%9}, {%0,%1,%2,%3};"
        : "+f"(d[0]), "+f"(d[1]), "+f"(d[2]), "+f"(d[3])
        : "r"(a[0]), "r"(a[1]), "r"(a[2]), "r"(a[3]), "r"(b0), "r"(b1));
}

// ---------------- fold W_dst·att_dst (dst side only) ----------------
__global__ void prep_v_kernel(const float* __restrict__ Wdl, const float* __restrict__ Wdg,
                              const float* __restrict__ adl, const float* __restrict__ adg) {
    int idx = blockIdx.x * blockDim.x + threadIdx.x;
    if (idx >= 3 * 2 * 128 * 4) return;
    int h = idx & 3, k = (idx >> 2) & 127, sc = (idx >> 9) & 1, rel = idx >> 10;
    const float* W = (sc ? Wdg : Wdl) + (size_t)rel * 128 * 128;
    const float* att = (sc ? adg : adl) + rel * 4 * 32;
    float s = 0.f;
#pragma unroll
    for (int c = 0; c < 32; c++) s += W[k * 128 + h * 32 + c] * att[h * 32 + c];
    g_vpack[((rel * 2 + 1) * 8 + sc * 4 + h) * 128 + k] = s;
}

// ---------------- a_dst = x_d @ v  (warp per node) ----------------
__global__ void compute_a_kernel(const float* __restrict__ x, int rel) {
    int node = (blockIdx.x * blockDim.x + threadIdx.x) >> 5;
    int lane = threadIdx.x & 31;
    if (node >= NN) return;
    const float* vp = &g_vpack[(size_t)(rel * 2 + 1) * 8 * 128];
    float4 x4 = *reinterpret_cast<const float4*>(&x[(size_t)node * 128 + lane * 4]);
    float p[8];
#pragma unroll
    for (int j = 0; j < 8; j++) {
        float4 v4 = *reinterpret_cast<const float4*>(&vp[j * 128 + lane * 4]);
        p[j] = x4.x * v4.x + x4.y * v4.y + x4.z * v4.z + x4.w * v4.w;
    }
#pragma unroll
    for (int d = 16; d > 0; d >>= 1)
#pragma unroll
        for (int j = 0; j < 8; j++) p[j] += __shfl_xor_sync(0xffffffffu, p[j], d);
    if (lane < 8) g_adP[rel][(size_t)node * 8 + lane] = p[lane];
}

// ---------------- bf16x3 tensor-core GEMM: C[M,128] = A[M,K] @ B[K,128] ----------------
// CTA tile 128x128, BK=16, 8 warps of 64x32, double-buffered smem, m16n8k16 bf16.
// Split: x = hi + lo (bf16 each); D = hi*hi + hi*lo + lo*hi (lo*lo ~2^-18 dropped).
// Optional epilogue: a_s[row, head=wn] = sum_c acc[row, wn*32+c] * attp[wn*32+c]
__global__ __launch_bounds__(256) void gemm_bf16x3_kernel(const float* __restrict__ A,
                                                          const float* __restrict__ B,
                                                          float* __restrict__ C, int M, int K,
                                                          const float* __restrict__ attp,
                                                          float* __restrict__ asP_out, int slot) {
    __shared__ uint32_t Ah2[2][8][136], Al2[2][8][136];   // [stage][k-pair][m]
    __shared__ uint32_t Bh2[2][8][136], Bl2[2][8][136];   // [stage][k-pair][n]
    const int tid = threadIdx.x;
    const int lane = tid & 31, warp = tid >> 5;
    const int wm = warp >> 2, wn = warp & 3;
    const int gr = lane >> 2, gk = lane & 3;
    const int m0 = blockIdx.x * 128;

    const int ar = tid & 127;
    const int ak8 = (tid >> 7) << 3;          // 0 or 8 (k sub-offset)
    const int arow = m0 + ar;
    const int k2b = ak8 >> 1;                 // base k-pair index (0 or 4)

    float acc[4][4][4];
#pragma unroll
    for (int mt = 0; mt < 4; mt++)
#pragma unroll
        for (int nt = 0; nt < 4; nt++)
#pragma unroll
            for (int e = 0; e < 4; e++) acc[mt][nt][e] = 0.f;

    const int NIT = K >> 4;

    auto stageA = [&](int st, float4 v0, float4 v1) {
        float h, l;
        h = bfhi(v0.x); l = v0.x - h;
        float h2 = bfhi(v0.y), l2 = v0.y - h2;
        Ah2[st][k2b][ar] = packbf(h, h2); Al2[st][k2b][ar] = packbf(l, l2);
        h = bfhi(v0.z); l = v0.z - h; h2 = bfhi(v0.w); l2 = v0.w - h2;
        Ah2[st][k2b + 1][ar] = packbf(h, h2); Al2[st][k2b + 1][ar] = packbf(l, l2);
        h = bfhi(v1.x); l = v1.x - h; h2 = bfhi(v1.y); l2 = v1.y - h2;
        Ah2[st][k2b + 2][ar] = packbf(h, h2); Al2[st][k2b + 2][ar] = packbf(l, l2);
        h = bfhi(v1.z); l = v1.z - h; h2 = bfhi(v1.w); l2 = v1.w - h2;
        Ah2[st][k2b + 3][ar] = packbf(h, h2); Al2[st][k2b + 3][ar] = packbf(l, l2);
    };
    auto stageB = [&](int st, float4 r0, float4 r1) {
        uint32_t oh[4], ol[4];
#pragma unroll
        for (int e = 0; e < 4; e++) {
            float x0 = (&r0.x)[e], x1 = (&r1.x)[e];
            float h0 = bfhi(x0), h1 = bfhi(x1);
            oh[e] = packbf(h0, h1);            // low = even k row
            ol[e] = packbf(x0 - h0, x1 - h1);
        }
        *reinterpret_cast<uint4*>(&Bh2[st][warp][lane * 4]) =
            make_uint4(oh[0], oh[1], oh[2], oh[3]);
        *reinterpret_cast<uint4*>(&Bl2[st][warp][lane * 4]) =
            make_uint4(ol[0], ol[1], ol[2], ol[3]);
    };

    // prologue: k-slab 0
    {
        float4 av0 = make_float4(0.f, 0.f, 0.f, 0.f), av1 = av0;
        if (arow < M) {
            av0 = *reinterpret_cast<const float4*>(&A[(size_t)arow * K + ak8]);
            av1 = *reinterpret_cast<const float4*>(&A[(size_t)arow * K + ak8 + 4]);
        }
        float4 bv0 = *reinterpret_cast<const float4*>(&B[(size_t)(2 * warp) * 128 + lane * 4]);
        float4 bv1 = *reinterpret_cast<const float4*>(&B[(size_t)(2 * warp + 1) * 128 + lane * 4]);
        stageA(0, av0, av1);
        stageB(0, bv0, bv1);
    }
    __syncthreads();

    int s = 0;
    for (int it = 0; it < NIT; it++) {
        float4 av0, av1, bv0, bv1;
        const bool more = (it + 1 < NIT);
        if (more) {
            int k0 = (it + 1) << 4;
            av0 = make_float4(0.f, 0.f, 0.f, 0.f); av1 = av0;
            if (arow < M) {
                av0 = *reinterpret_cast<const float4*>(&A[(size_t)arow * K + k0 + ak8]);
                av1 = *reinterpret_cast<const float4*>(&A[(size_t)arow * K + k0 + ak8 + 4]);
            }
            bv0 = *reinterpret_cast<const float4*>(&B[(size_t)(k0 + 2 * warp) * 128 + lane * 4]);
            bv1 = *reinterpret_cast<const float4*>(&B[(size_t)(k0 + 2 * warp + 1) * 128 + lane * 4]);
        }

        uint32_t afrag[4][4];
#pragma unroll
        for (int mt = 0; mt < 4; mt++) {          // A hi fragments
            int r = wm * 64 + mt * 16 + gr;
            afrag[mt][0] = Ah2[s][gk][r];     afrag[mt][1] = Ah2[s][gk][r + 8];
            afrag[mt][2] = Ah2[s][gk + 4][r]; afrag[mt][3] = Ah2[s][gk + 4][r + 8];
        }
#pragma unroll
        for (int nt = 0; nt < 4; nt++) {          // pass 1: hi*hi
            int c = wn * 32 + nt * 8 + gr;
            uint32_t b0 = Bh2[s][gk][c], b1 = Bh2[s][gk + 4][c];
#pragma unroll
            for (int mt = 0; mt < 4; mt++) mma_bf16(acc[mt][nt], afrag[mt], b0, b1);
        }
#pragma unroll
        for (int nt = 0; nt < 4; nt++) {          // pass 2: hi*lo
            int c = wn * 32 + nt * 8 + gr;
            uint32_t b0 = Bl2[s][gk][c], b1 = Bl2[s][gk + 4][c];
#pragma unroll
            for (int mt = 0; mt < 4; mt++) mma_bf16(acc[mt][nt], afrag[mt], b0, b1);
        }
#pragma unroll
        for (int mt = 0; mt < 4; mt++) {          // A lo fragments
            int r = wm * 64 + mt * 16 + gr;
            afrag[mt][0] = Al2[s][gk][r];     afrag[mt][1] = Al2[s][gk][r + 8];
            afrag[mt][2] = Al2[s][gk + 4][r]; afrag[mt][3] = Al2[s][gk + 4][r + 8];
        }
#pragma unroll
        for (int nt = 0; nt < 4; nt++) {          // pass 3: lo*hi
            int c = wn * 32 + nt * 8 + gr;
            uint32_t b0 = Bh2[s][gk][c], b1 = Bh2[s][gk + 4][c];
#pragma unroll
            for (int mt = 0; mt < 4; mt++) mma_bf16(acc[mt][nt], afrag[mt], b0, b1);
        }

        if (more) {
            int d = s ^ 1;
            stageA(d, av0, av1);
            stageB(d, bv0, bv1);
        }
        __syncthreads();
        s ^= 1;
    }

    // ---- epilogue: store C ----
#pragma unroll
    for (int mt = 0; mt < 4; mt++) {
        int row0 = m0 + wm * 64 + mt * 16 + gr;
        int row1 = row0 + 8;
#pragma unroll
        for (int nt = 0; nt < 4; nt++) {
            int col = wn * 32 + nt * 8 + gk * 2;
            if (row0 < M)
                *reinterpret_cast<float2*>(&C[(size_t)row0 * 128 + col]) =
                    make_float2(acc[mt][nt][0], acc[mt][nt][1]);
            if (row1 < M)
                *reinterpret_cast<float2*>(&C[(size_t)row1 * 128 + col]) =
                    make_float2(acc[mt][nt][2], acc[mt][nt][3]);
        }
    }

    // ---- fused a_src epilogue ----
    if (attp) {
        float attv[4][2];
#pragma unroll
        for (int nt = 0; nt < 4; nt++) {
            attv[nt][0] = attp[wn * 32 + nt * 8 + gk * 2];
            attv[nt][1] = attp[wn * 32 + nt * 8 + gk * 2 + 1];
        }
#pragma unroll
        for (int mt = 0; mt < 4; mt++) {
            float s0 = 0.f, s1 = 0.f;
#pragma unroll
            for (int nt = 0; nt < 4; nt++) {
                s0 += acc[mt][nt][0] * attv[nt][0] + acc[mt][nt][1] * attv[nt][1];
                s1 += acc[mt][nt][2] * attv[nt][0] + acc[mt][nt][3] * attv[nt][1];
            }
            s0 += __shfl_xor_sync(0xffffffffu, s0, 1);
            s0 += __shfl_xor_sync(0xffffffffu, s0, 2);
            s1 += __shfl_xor_sync(0xffffffffu, s1, 1);
            s1 += __shfl_xor_sync(0xffffffffu, s1, 2);
            if (gk == 0) {
                int row0 = m0 + wm * 64 + mt * 16 + gr;
                if (row0 < M) asP_out[(size_t)row0 * 8 + slot + wn] = s0;
                if (row0 + 8 < M) asP_out[(size_t)(row0 + 8) * 8 + slot + wn] = s1;
            }
        }
    }
}

// ---------------- fused gate GEMM (bf16x3): builds cat on the fly, applies sigmoid gate ----
__global__ __launch_bounds__(256) void gatefuse_kernel(int t,
                                                       const float* __restrict__ bl,
                                                       const float* __restrict__ bg,
                                                       const float* __restrict__ rg,
                                                       const float* __restrict__ gW,
                                                       const float* __restrict__ gb) {
    __shared__ uint32_t Ah2[2][8][136], Al2[2][8][136];
    __shared__ uint32_t Bh2[2][8][136], Bl2[2][8][136];
    const int tid = threadIdx.x;
    const int lane = tid & 31, warp = tid >> 5;
    const int wm = warp >> 2, wn = warp & 3;
    const int gr = lane >> 2, gk = lane & 3;
    const int m0 = blockIdx.x * 128;
    const int K = 256;

    float w0 = 1.f, w1 = 0.f;
    if (t == 0) {
        float r0 = rg[0], r1 = rg[1];
        float m = fmaxf(r0, r1);
        float e0 = __expf(r0 - m), e1 = __expf(r1 - m);
        float inv = 1.f / (e0 + e1);
        w0 = e0 * inv; w1 = e1 * inv;
    }
    const float* B = gW + (size_t)t * 32768;
    const float* gbt = gb + t * 128;
    float* fus = &g_fus[t][0];

    const int ar = tid & 127;
    const int ak8 = (tid >> 7) << 3;
    const int arow = m0 + ar;
    const int k2b = ak8 >> 1;

    auto loadA = [&](int cc) -> float4 {
        float4 v = make_float4(0.f, 0.f, 0.f, 0.f);
        if (arow >= NN) return v;
        if (cc < 128) {
            if (t == 0) {
                float4 a2 = *reinterpret_cast<const float4*>(&g_agg[2][(size_t)arow * 128 + cc]);
                float4 a4 = *reinterpret_cast<const float4*>(&g_agg[4][(size_t)arow * 128 + cc]);
                float4 b1 = *reinterpret_cast<const float4*>(&bl[128 + cc]);
                float4 b2 = *reinterpret_cast<const float4*>(&bl[256 + cc]);
#pragma unroll
                for (int e = 0; e < 4; e++)
                    (&v.x)[e] = w0 * ((&a2.x)[e] + (&b1.x)[e]) + w1 * ((&a4.x)[e] + (&b2.x)[e]);
            } else {
                float4 a0 = *reinterpret_cast<const float4*>(&g_agg[0][(size_t)arow * 128 + cc]);
                float4 b0 = *reinterpret_cast<const float4*>(&bl[cc]);
#pragma unroll
                for (int e = 0; e < 4; e++) (&v.x)[e] = (&a0.x)[e] + (&b0.x)[e];
            }
        } else {
            int c = cc - 128;
            if (t == 0) {
                float4 a3 = *reinterpret_cast<const float4*>(&g_agg[3][(size_t)arow * 128 + c]);
                float4 a5 = *reinterpret_cast<const float4*>(&g_agg[5][(size_t)arow * 128 + c]);
                float4 b1 = *reinterpret_cast<const float4*>(&bg[128 + c]);
                float4 b2 = *reinterpret_cast<const float4*>(&bg[256 + c]);
#pragma unroll
                for (int e = 0; e < 4; e++)
                    (&v.x)[e] = w0 * ((&a3.x)[e] + (&b1.x)[e]) + w1 * ((&a5.x)[e] + (&b2.x)[e]);
            } else {
                float4 a1 = *reinterpret_cast<const float4*>(&g_agg[1][(size_t)arow * 128 + c]);
                float4 b0 = *reinterpret_cast<const float4*>(&bg[c]);
#pragma unroll
                for (int e = 0; e < 4; e++) (&v.x)[e] = (&a1.x)[e] + (&b0.x)[e];
            }
        }
        return v;
    };

    auto stageA = [&](int st, float4 v0, float4 v1) {
        float h, l, h2, l2;
        h = bfhi(v0.x); l = v0.x - h; h2 = bfhi(v0.y); l2 = v0.y - h2;
        Ah2[st][k2b][ar] = packbf(h, h2); Al2[st][k2b][ar] = packbf(l, l2);
        h = bfhi(v0.z); l = v0.z - h; h2 = bfhi(v0.w); l2 = v0.w - h2;
        Ah2[st][k2b + 1][ar] = packbf(h, h2); Al2[st][k2b + 1][ar] = packbf(l, l2);
        h = bfhi(v1.x); l = v1.x - h; h2 = bfhi(v1.y); l2 = v1.y - h2;
        Ah2[st][k2b + 2][ar] = packbf(h, h2); Al2[st][k2b + 2][ar] = packbf(l, l2);
        h = bfhi(v1.z); l = v1.z - h; h2 = bfhi(v1.w); l2 = v1.w - h2;
        Ah2[st][k2b + 3][ar] = packbf(h, h2); Al2[st][k2b + 3][ar] = packbf(l, l2);
    };
    auto stageB = [&](int st, float4 r0, float4 r1) {
        uint32_t oh[4], ol[4];
#pragma unroll
        for (int e = 0; e < 4; e++) {
            float x0 = (&r0.x)[e], x1 = (&r1.x)[e];
            float h0 = bfhi(x0), h1 = bfhi(x1);
            oh[e] = packbf(h0, h1);
            ol[e] = packbf(x0 - h0, x1 - h1);
        }
        *reinterpret_cast<uint4*>(&Bh2[st][warp][lane * 4]) =
            make_uint4(oh[0], oh[1], oh[2], oh[3]);
        *reinterpret_cast<uint4*>(&Bl2[st][warp][lane * 4]) =
            make_uint4(ol[0], ol[1], ol[2], ol[3]);
    };

    float acc[4][4][4];
#pragma unroll
    for (int mt = 0; mt < 4; mt++)
#pragma unroll
        for (int nt = 0; nt < 4; nt++)
#pragma unroll
            for (int e = 0; e < 4; e++) acc[mt][nt][e] = 0.f;

    const int NIT = K >> 4;

    {
        float4 av0 = loadA(ak8), av1 = loadA(ak8 + 4);
        float4 bv0 = *reinterpret_cast<const float4*>(&B[(size_t)(2 * warp) * 128 + lane * 4]);
        float4 bv1 = *reinterpret_cast<const float4*>(&B[(size_t)(2 * warp + 1) * 128 + lane * 4]);
        stageA(0, av0, av1);
        stageB(0, bv0, bv1);
    }
    __syncthreads();

    int s = 0;
    for (int it = 0; it < NIT; it++) {
        float4 av0, av1, bv0, bv1;
        const bool more = (it + 1 < NIT);
        if (more) {
            int k0 = (it + 1) << 4;
            av0 = loadA(k0 + ak8); av1 = loadA(k0 + ak8 + 4);
            bv0 = *reinterpret_cast<const float4*>(&B[(size_t)(k0 + 2 * warp) * 128 + lane * 4]);
            bv1 = *reinterpret_cast<const float4*>(&B[(size_t)(k0 + 2 * warp + 1) * 128 + lane * 4]);
        }

        uint32_t afrag[4][4];
#pragma unroll
        for (int mt = 0; mt < 4; mt++) {
            int r = wm * 64 + mt * 16 + gr;
            afrag[mt][0] = Ah2[s][gk][r];     afrag[mt][1] = Ah2[s][gk][r + 8];
            afrag[mt][2] = Ah2[s][gk + 4][r]; afrag[mt][3] = Ah2[s][gk + 4][r + 8];
        }
#pragma unroll
        for (int nt = 0; nt < 4; nt++) {
            int c = wn * 32 + nt * 8 + gr;
            uint32_t b0 = Bh2[s][gk][c], b1 = Bh2[s][gk + 4][c];
#pragma unroll
            for (int mt = 0; mt < 4; mt++) mma_bf16(acc[mt][nt], afrag[mt], b0, b1);
        }
#pragma unroll
        for (int nt = 0; nt < 4; nt++) {
            int c = wn * 32 + nt * 8 + gr;
            uint32_t b0 = Bl2[s][gk][c], b1 = Bl2[s][gk + 4][c];
#pragma unroll
            for (int mt = 0; mt < 4; mt++) mma_bf16(acc[mt][nt], afrag[mt], b0, b1);
        }
#pragma unroll
        for (int mt = 0; mt < 4; mt++) {
            int r = wm * 64 + mt * 16 + gr;
            afrag[mt][0] = Al2[s][gk][r];     afrag[mt][1] = Al2[s][gk][r + 8];
            afrag[mt][2] = Al2[s][gk + 4][r]; afrag[mt][3] = Al2[s][gk + 4][r + 8];
        }
#pragma unroll
        for (int nt = 0; nt < 4; nt++) {
            int c = wn * 32 + nt * 8 + gr;
            uint32_t b0 = Bh2[s][gk][c], b1 = Bh2[s][gk + 4][c];
#pragma unroll
            for (int mt = 0; mt < 4; mt++) mma_bf16(acc[mt][nt], afrag[mt], b0, b1);
        }

        if (more) {
            int d = s ^ 1;
            stageA(d, av0, av1);
            stageB(d, bv0, bv1);
        }
        __syncthreads();
        s ^= 1;
    }

    // epilogue: sigmoid gate, recompute loc/glb, write fus
#pragma unroll
    for (int mt = 0; mt < 4; mt++) {
#pragma unroll
        for (int half = 0; half < 2; half++) {
            int row = m0 + wm * 64 + mt * 16 + gr + half * 8;
            if (row >= NN) continue;
#pragma unroll
            for (int nt = 0; nt < 4; nt++) {
                int col = wn * 32 + nt * 8 + gk * 2;
                float gl0 = acc[mt][nt][half * 2 + 0] + gbt[col];
                float gl1 = acc[mt][nt][half * 2 + 1] + gbt[col + 1];
                float s0 = 1.f / (1.f + __expf(-gl0));
                float s1 = 1.f / (1.f + __expf(-gl1));
                float2 loc, glb;
                if (t == 0) {
                    float2 a2 = *reinterpret_cast<const float2*>(&g_agg[2][(size_t)row * 128 + col]);
                    float2 a4 = *reinterpret_cast<const float2*>(&g_agg[4][(size_t)row * 128 + col]);
                    float2 a3 = *reinterpret_cast<const float2*>(&g_agg[3][(size_t)row * 128 + col]);
                    float2 a5 = *reinterpret_cast<const float2*>(&g_agg[5][(size_t)row * 128 + col]);
                    loc.x = w0 * (a2.x + bl[128 + col]) + w1 * (a4.x + bl[256 + col]);
                    loc.y = w0 * (a2.y + bl[128 + col + 1]) + w1 * (a4.y + bl[256 + col + 1]);
                    glb.x = w0 * (a3.x + bg[128 + col]) + w1 * (a5.x + bg[256 + col]);
                    glb.y = w0 * (a3.y + bg[128 + col + 1]) + w1 * (a5.y + bg[256 + col + 1]);
                } else {
                    float2 a0 = *reinterpret_cast<const float2*>(&g_agg[0][(size_t)row * 128 + col]);
                    float2 a1 = *reinterpret_cast<const float2*>(&g_agg[1][(size_t)row * 128 + col]);
                    loc.x = a0.x + bl[col];     loc.y = a0.y + bl[col + 1];
                    glb.x = a1.x + bg[col];     glb.y = a1.y + bg[col + 1];
                }
                float2 o;
                o.x = s0 * loc.x + (1.f - s0) * glb.x;
                o.y = s1 * loc.y + (1.f - s1) * glb.y;
                *reinterpret_cast<float2*>(&fus[(size_t)row * 128 + col]) = o;
            }
        }
    }
}

// ---------------- merged CSR build (all 3 relations) ----------------
#define ETOT (3 * EE + NN)
__global__ void zero_all_kernel() {
    int i = blockIdx.x * blockDim.x + threadIdx.x;
    if (i < 3 * NN) { (&g_deg[0][0])[i] = 0; (&g_cur[0][0])[i] = 0; }
}
__device__ __forceinline__ void edge_decode(int i, const int* eb, const int* er, const int* ef,
                                            int& rel, int& s, int& d) {
    if (i < EE) { rel = 0; s = eb[i]; d = eb[EE + i]; }
    else if (i < 2 * EE) { rel = 1; int j = i - EE; s = er[j]; d = er[EE + j]; }
    else { int j = i - 2 * EE; rel = 2;
           if (j < EE) { s = ef[j]; d = ef[EE + j]; } else { s = d = j - EE; } }
}
__global__ void count_all_kernel(const int* __restrict__ eb, const int* __restrict__ er,
                                 const int* __restrict__ ef) {
    int i = blockIdx.x * blockDim.x + threadIdx.x;
    if (i >= ETOT) return;
    int rel, s, d; edge_decode(i, eb, er, ef, rel, s, d);
    atomicAdd(&g_deg[rel][d], 1);
}
#define GSCAN ((NN + 1023) / 1024)
__global__ void scan1_all_kernel() {
    __shared__ int s[1024];
    int rel = blockIdx.x / GSCAN, blk = blockIdx.x % GSCAN;
    int tid = threadIdx.x;
    int i = blk * 1024 + tid;
    int v = (i < NN) ? g_deg[rel][i] : 0;
    s[tid] = v; __syncthreads();
    for (int d = 1; d < 1024; d <<= 1) {
        int t = (tid >= d) ? s[tid - d] : 0;
        __syncthreads();
        s[tid] += t; __syncthreads();
    }
    if (i < NN) g_off[rel][i] = s[tid] - v;
    if (tid == 1023) g_part[rel][blk] = s[1023];
}
__global__ void scan2_all_kernel() {
    __shared__ int s[128];
    int rel = blockIdx.x;
    int tid = threadIdx.x;
    int v = (tid < GSCAN) ? g_part[rel][tid] : 0;
    s[tid] = v; __syncthreads();
    for (int d = 1; d < 128; d <<= 1) {
        int t = (tid >= d) ? s[tid - d] : 0;
        __syncthreads();
        s[tid] += t; __syncthreads();
    }
    if (tid < GSCAN) g_part[rel][tid] = s[tid] - v;
    if (tid == 127) g_off[rel][NN] = s[127];
}
__global__ void scan3_all_kernel() {
    int rel = blockIdx.x / GSCAN, blk = blockIdx.x % GSCAN;
    int i = blk * 1024 + threadIdx.x;
    if (i < NN) g_off[rel][i] += g_part[rel][blk];
}
__global__ void fill_all_kernel(const int* __restrict__ eb, const int* __restrict__ er,
                                const int* __restrict__ ef) {
    int i = blockIdx.x * blockDim.x + threadIdx.x;
    if (i >= ETOT) return;
    int rel, s, d; edge_decode(i, eb, er, ef, rel, s, d);
    int pos = atomicAdd(&g_cur[rel][d], 1);
    g_csr[rel][g_off[rel][d] + pos] = s;
}

// ---------------- softmax-attention aggregation: warp per dst node, one scale ----------------
// unrolled x2 for memory-level parallelism on the 512B hs gathers
__global__ void agg_kernel(int rel, int sc, float slope) {
    int node = blockIdx.x * 8 + (threadIdx.x >> 5);
    int lane = threadIdx.x & 31;
    if (node >= NN) return;
    const float* __restrict__ hsv = g_hs[rel * 2 + sc];
    const int* __restrict__ csr = g_csr[rel];
    int beg = g_off[rel][node], end = g_off[rel][node + 1];
    float adv = (lane < 4) ? g_adP[rel][(size_t)node * 8 + sc * 4 + lane] : 0.f;
    int h = lane >> 3;
    float4 a = make_float4(0.f, 0.f, 0.f, 0.f);
    float den = 0.f;
    int i = beg;
    for (; i + 1 < end; i += 2) {
        int s0 = __ldg(&csr[i]), s1 = __ldg(&csr[i + 1]);
        float as0 = (lane < 4) ? __ldg(&g_asP[rel][(size_t)s0 * 8 + sc * 4 + lane]) : 0.f;
        float as1 = (lane < 4) ? __ldg(&g_asP[rel][(size_t)s1 * 8 + sc * 4 + lane]) : 0.f;
        float4 h0 = *reinterpret_cast<const float4*>(&hsv[(size_t)s0 * 128 + lane * 4]);
        float4 h1 = *reinterpret_cast<const float4*>(&hsv[(size_t)s1 * 128 + lane * 4]);
        float sum0 = as0 + adv, sum1 = as1 + adv;
        float sv0 = __shfl_sync(0xffffffffu, sum0, h);
        float sv1 = __shfl_sync(0xffffffffu, sum1, h);
        float e0 = sv0 > 0.f ? sv0 : slope * sv0;
        float e1 = sv1 > 0.f ? sv1 : slope * sv1;
        float w0 = __expf(e0), w1 = __expf(e1);
        den += w0 + w1;
        a.x += w0 * h0.x + w1 * h1.x;
        a.y += w0 * h0.y + w1 * h1.y;
        a.z += w0 * h0.z + w1 * h1.z;
        a.w += w0 * h0.w + w1 * h1.w;
    }
    if (i < end) {
        int s0 = __ldg(&csr[i]);
        float as0 = (lane < 4) ? __ldg(&g_asP[rel][(size_t)s0 * 8 + sc * 4 + lane]) : 0.f;
        float4 h0 = *reinterpret_cast<const float4*>(&hsv[(size_t)s0 * 128 + lane * 4]);
        float sum0 = as0 + adv;
        float sv0 = __shfl_sync(0xffffffffu, sum0, h);
        float e0 = sv0 > 0.f ? sv0 : slope * sv0;
        float w0 = __expf(e0);
        den += w0;
        a.x += w0 * h0.x; a.y += w0 * h0.y; a.z += w0 * h0.z; a.w += w0 * h0.w;
    }
    float inv = 1.f / (den + 1e-16f);
    float4 o = make_float4(a.x * inv, a.y * inv, a.z * inv, a.w * inv);
    *reinterpret_cast<float4*>(&g_agg[rel * 2 + sc][(size_t)node * 128 + lane * 4]) = o;
}

// ---------------- launch ----------------
extern "C" void kernel_launch(void* const* d_in, const int* in_sizes, int n_in,
                              void* d_out, int out_size) {
    const float* x_user = (const float*)d_in[0];
    const float* x_item = (const float*)d_in[1];
    const float* Wsl = (const float*)d_in[2];
    const float* Wdl = (const float*)d_in[3];
    const float* asl = (const float*)d_in[4];
    const float* adl = (const float*)d_in[5];
    const float* bl  = (const float*)d_in[6];
    const float* Wsg = (const float*)d_in[7];
    const float* Wdg = (const float*)d_in[8];
    const float* asg = (const float*)d_in[9];
    const float* adg = (const float*)d_in[10];
    const float* bg  = (const float*)d_in[11];
    const float* gW  = (const float*)d_in[12];
    const float* gb  = (const float*)d_in[13];
    const float* oW  = (const float*)d_in[14];
    const float* rg  = (const float*)d_in[15];
    const int* ei_buys    = (const int*)d_in[16];
    const int* ei_rev     = (const int*)d_in[17];
    const int* ei_follows = (const int*)d_in[18];
    float* out = (float*)d_out;

    float *hs_base, *asP_base, *fus_base;
    cudaGetSymbolAddress((void**)&hs_base, g_hs);
    cudaGetSymbolAddress((void**)&asP_base, g_asP);
    cudaGetSymbolAddress((void**)&fus_base, g_fus);

    const int GA = (NN * 32 + 255) / 256;
    const int GB = (NN + 127) / 128;

    prep_v_kernel<<<(3072 + 255) / 256, 256>>>(Wdl, Wdg, adl, adg);

    // dst-side attention logits
    compute_a_kernel<<<GA, 256>>>(x_item, 0);
    compute_a_kernel<<<GA, 256>>>(x_user, 1);
    compute_a_kernel<<<GA, 256>>>(x_user, 2);

    // CSR build (merged)
    zero_all_kernel<<<(3 * NN + 255) / 256, 256>>>();
    count_all_kernel<<<(ETOT + 255) / 256, 256>>>(ei_buys, ei_rev, ei_follows);
    scan1_all_kernel<<<3 * GSCAN, 1024>>>();
    scan2_all_kernel<<<3, 128>>>();
    scan3_all_kernel<<<3 * GSCAN, 1024>>>();
    fill_all_kernel<<<(ETOT + 255) / 256, 256>>>(ei_buys, ei_rev, ei_follows);

    // src projections hs (6 GEMMs, bf16x3) with fused a_src epilogue
    gemm_bf16x3_kernel<<<GB, 256>>>(x_user, Wsl + 0 * 16384, hs_base + (size_t)0 * NN * 128, NN, 128,
                                    asl + 0 * 128, asP_base + (size_t)0 * NN * 8, 0);
    gemm_bf16x3_kernel<<<GB, 256>>>(x_user, Wsg + 0 * 16384, hs_base + (size_t)1 * NN * 128, NN, 128,
                                    asg + 0 * 128, asP_base + (size_t)0 * NN * 8, 4);
    gemm_bf16x3_kernel<<<GB, 256>>>(x_item, Wsl + 1 * 16384, hs_base + (size_t)2 * NN * 128, NN, 128,
                                    asl + 1 * 128, asP_base + (size_t)1 * NN * 8, 0);
    gemm_bf16x3_kernel<<<GB, 256>>>(x_item, Wsg + 1 * 16384, hs_base + (size_t)3 * NN * 128, NN, 128,
                                    asg + 1 * 128, asP_base + (size_t)1 * NN * 8, 4);
    gemm_bf16x3_kernel<<<GB, 256>>>(x_user, Wsl + 2 * 16384, hs_base + (size_t)4 * NN * 128, NN, 128,
                                    asl + 2 * 128, asP_base + (size_t)2 * NN * 8, 0);
    gemm_bf16x3_kernel<<<GB, 256>>>(x_user, Wsg + 2 * 16384, hs_base + (size_t)5 * NN * 128, NN, 128,
                                    asg + 2 * 128, asP_base + (size_t)2 * NN * 8, 4);

    // aggregation: one (relation, scale) per launch
    for (int r = 0; r < 3; r++) {
        agg_kernel<<<(NN + 7) / 8, 256>>>(r, 0, 0.2f);
        agg_kernel<<<(NN + 7) / 8, 256>>>(r, 1, 0.3f);
    }

    // fused gate+sigmoid+mix
    gatefuse_kernel<<<GB, 256>>>(0, bl, bg, rg, gW, gb);
    gatefuse_kernel<<<GB, 256>>>(1, bl, bg, rg, gW, gb);

    // output GEMMs
    gemm_bf16x3_kernel<<<GB, 256>>>(fus_base + (size_t)0 * NN * 128, oW + 0 * 16384, out, NN, 128,
                                    nullptr, nullptr, 0);
    gemm_bf16x3_kernel<<<GB, 256>>>(fus_base + (size_t)1 * NN * 128, oW + 1 * 16384,
                                    out + (size_t)NN * 128, NN, 128, nullptr, nullptr, 0);
}

// round 7
// speedup vs baseline: 1.9662x; 1.0756x over previous
#include <cuda_runtime.h>
#include <cuda_bf16.h>
#include <cuda_fp16.h>
#include <cstdint>

#define NN 100000
#define EE 1000000

// ---------------- scratch (__device__ globals; no allocation allowed) ----------------
__device__ __half g_hsh[6][NN * 128];   // projected src features per (rel, scale), fp16
__device__ float g_agg[6][NN * 128];    // normalized aggregation per (rel, scale)
__device__ float g_asP[3][NN * 8];      // a_src packed [node][local h0..3, global h0..3]
__device__ float g_adP[3][NN * 8];      // a_dst packed
__device__ float g_vpack[3 * 2 * 8 * 128]; // folded W_dst·att_dst vectors
__device__ int   g_deg[3][NN];
__device__ int   g_cur[3][NN];
__device__ int   g_off[3][NN + 1];
__device__ int   g_part[3][256];
__device__ int   g_csr[3][EE + NN];
__device__ float g_fus[2][NN * 128];    // fused features

// ---------------- helpers ----------------
__device__ __forceinline__ uint32_t packbf(float lo, float hi) {
    uint32_t r;
    asm("cvt.rn.bf16x2.f32 %0, %1, %2;" : "=r"(r) : "f"(hi), "f"(lo));
    return r;
}
__device__ __forceinline__ float bfhi(float x) {
    return __bfloat162float(__float2bfloat16_rn(x));
}

__device__ __forceinline__ void mma_bf16(float* d, const uint32_t* a, uint32_t b0, uint32_t b1) {
    asm volatile(
        "mma.sync.aligned.m16n8k16.row.col.f32.bf16.bf16.f32 "
        "{%0,%1,%2,%3}, {%4,%5,%6,%7}, {%8,%9}, {%0,%1,%2,%3};"
        : "+f"(d[0]), "+f"(d[1]), "+f"(d[2]), "+f"(d[3])
        : "r"(a[0]), "r"(a[1]), "r"(a[2]), "r"(a[3]), "r"(b0), "r"(b1));
}

// ---------------- fold W_dst·att_dst (dst side only) ----------------
__global__ void prep_v_kernel(const float* __restrict__ Wdl, const float* __restrict__ Wdg,
                              const float* __restrict__ adl, const float* __restrict__ adg) {
    int idx = blockIdx.x * blockDim.x + threadIdx.x;
    if (idx >= 3 * 2 * 128 * 4) return;
    int h = idx & 3, k = (idx >> 2) & 127, sc = (idx >> 9) & 1, rel = idx >> 10;
    const float* W = (sc ? Wdg : Wdl) + (size_t)rel * 128 * 128;
    const float* att = (sc ? adg : adl) + rel * 4 * 32;
    float s = 0.f;
#pragma unroll
    for (int c = 0; c < 32; c++) s += W[k * 128 + h * 32 + c] * att[h * 32 + c];
    g_vpack[((rel * 2 + 1) * 8 + sc * 4 + h) * 128 + k] = s;
}

// ---------------- a_dst = x_d @ v  (warp per node) ----------------
__global__ void compute_a_kernel(const float* __restrict__ x, int rel) {
    int node = (blockIdx.x * blockDim.x + threadIdx.x) >> 5;
    int lane = threadIdx.x & 31;
    if (node >= NN) return;
    const float* vp = &g_vpack[(size_t)(rel * 2 + 1) * 8 * 128];
    float4 x4 = *reinterpret_cast<const float4*>(&x[(size_t)node * 128 + lane * 4]);
    float p[8];
#pragma unroll
    for (int j = 0; j < 8; j++) {
        float4 v4 = *reinterpret_cast<const float4*>(&vp[j * 128 + lane * 4]);
        p[j] = x4.x * v4.x + x4.y * v4.y + x4.z * v4.z + x4.w * v4.w;
    }
#pragma unroll
    for (int d = 16; d > 0; d >>= 1)
#pragma unroll
        for (int j = 0; j < 8; j++) p[j] += __shfl_xor_sync(0xffffffffu, p[j], d);
    if (lane < 8) g_adP[rel][(size_t)node * 8 + lane] = p[lane];
}

// ---------------- bf16x3 tensor-core GEMM: C[M,128] = A[M,K] @ B[K,128] ----------------
// CTA tile 128x128, BK=16, 8 warps of 64x32, double-buffered smem, m16n8k16 bf16.
// Output: fp16 (Chalf) when given, else fp32 (C).
// Optional epilogue: a_s[row, head=wn] = sum_c acc[row, wn*32+c] * attp[wn*32+c]
__global__ __launch_bounds__(256) void gemm_bf16x3_kernel(const float* __restrict__ A,
                                                          const float* __restrict__ B,
                                                          float* __restrict__ C,
                                                          __half* __restrict__ Chalf,
                                                          int M, int K,
                                                          const float* __restrict__ attp,
                                                          float* __restrict__ asP_out, int slot) {
    __shared__ uint32_t Ah2[2][8][136], Al2[2][8][136];   // [stage][k-pair][m]
    __shared__ uint32_t Bh2[2][8][136], Bl2[2][8][136];   // [stage][k-pair][n]
    const int tid = threadIdx.x;
    const int lane = tid & 31, warp = tid >> 5;
    const int wm = warp >> 2, wn = warp & 3;
    const int gr = lane >> 2, gk = lane & 3;
    const int m0 = blockIdx.x * 128;

    const int ar = tid & 127;
    const int ak8 = (tid >> 7) << 3;
    const int arow = m0 + ar;
    const int k2b = ak8 >> 1;

    float acc[4][4][4];
#pragma unroll
    for (int mt = 0; mt < 4; mt++)
#pragma unroll
        for (int nt = 0; nt < 4; nt++)
#pragma unroll
            for (int e = 0; e < 4; e++) acc[mt][nt][e] = 0.f;

    const int NIT = K >> 4;

    auto stageA = [&](int st, float4 v0, float4 v1) {
        float h, l;
        h = bfhi(v0.x); l = v0.x - h;
        float h2 = bfhi(v0.y), l2 = v0.y - h2;
        Ah2[st][k2b][ar] = packbf(h, h2); Al2[st][k2b][ar] = packbf(l, l2);
        h = bfhi(v0.z); l = v0.z - h; h2 = bfhi(v0.w); l2 = v0.w - h2;
        Ah2[st][k2b + 1][ar] = packbf(h, h2); Al2[st][k2b + 1][ar] = packbf(l, l2);
        h = bfhi(v1.x); l = v1.x - h; h2 = bfhi(v1.y); l2 = v1.y - h2;
        Ah2[st][k2b + 2][ar] = packbf(h, h2); Al2[st][k2b + 2][ar] = packbf(l, l2);
        h = bfhi(v1.z); l = v1.z - h; h2 = bfhi(v1.w); l2 = v1.w - h2;
        Ah2[st][k2b + 3][ar] = packbf(h, h2); Al2[st][k2b + 3][ar] = packbf(l, l2);
    };
    auto stageB = [&](int st, float4 r0, float4 r1) {
        uint32_t oh[4], ol[4];
#pragma unroll
        for (int e = 0; e < 4; e++) {
            float x0 = (&r0.x)[e], x1 = (&r1.x)[e];
            float h0 = bfhi(x0), h1 = bfhi(x1);
            oh[e] = packbf(h0, h1);
            ol[e] = packbf(x0 - h0, x1 - h1);
        }
        *reinterpret_cast<uint4*>(&Bh2[st][warp][lane * 4]) =
            make_uint4(oh[0], oh[1], oh[2], oh[3]);
        *reinterpret_cast<uint4*>(&Bl2[st][warp][lane * 4]) =
            make_uint4(ol[0], ol[1], ol[2], ol[3]);
    };

    {
        float4 av0 = make_float4(0.f, 0.f, 0.f, 0.f), av1 = av0;
        if (arow < M) {
            av0 = *reinterpret_cast<const float4*>(&A[(size_t)arow * K + ak8]);
            av1 = *reinterpret_cast<const float4*>(&A[(size_t)arow * K + ak8 + 4]);
        }
        float4 bv0 = *reinterpret_cast<const float4*>(&B[(size_t)(2 * warp) * 128 + lane * 4]);
        float4 bv1 = *reinterpret_cast<const float4*>(&B[(size_t)(2 * warp + 1) * 128 + lane * 4]);
        stageA(0, av0, av1);
        stageB(0, bv0, bv1);
    }
    __syncthreads();

    int s = 0;
    for (int it = 0; it < NIT; it++) {
        float4 av0, av1, bv0, bv1;
        const bool more = (it + 1 < NIT);
        if (more) {
            int k0 = (it + 1) << 4;
            av0 = make_float4(0.f, 0.f, 0.f, 0.f); av1 = av0;
            if (arow < M) {
                av0 = *reinterpret_cast<const float4*>(&A[(size_t)arow * K + k0 + ak8]);
                av1 = *reinterpret_cast<const float4*>(&A[(size_t)arow * K + k0 + ak8 + 4]);
            }
            bv0 = *reinterpret_cast<const float4*>(&B[(size_t)(k0 + 2 * warp) * 128 + lane * 4]);
            bv1 = *reinterpret_cast<const float4*>(&B[(size_t)(k0 + 2 * warp + 1) * 128 + lane * 4]);
        }

        uint32_t afrag[4][4];
#pragma unroll
        for (int mt = 0; mt < 4; mt++) {
            int r = wm * 64 + mt * 16 + gr;
            afrag[mt][0] = Ah2[s][gk][r];     afrag[mt][1] = Ah2[s][gk][r + 8];
            afrag[mt][2] = Ah2[s][gk + 4][r]; afrag[mt][3] = Ah2[s][gk + 4][r + 8];
        }
#pragma unroll
        for (int nt = 0; nt < 4; nt++) {
            int c = wn * 32 + nt * 8 + gr;
            uint32_t b0 = Bh2[s][gk][c], b1 = Bh2[s][gk + 4][c];
#pragma unroll
            for (int mt = 0; mt < 4; mt++) mma_bf16(acc[mt][nt], afrag[mt], b0, b1);
        }
#pragma unroll
        for (int nt = 0; nt < 4; nt++) {
            int c = wn * 32 + nt * 8 + gr;
            uint32_t b0 = Bl2[s][gk][c], b1 = Bl2[s][gk + 4][c];
#pragma unroll
            for (int mt = 0; mt < 4; mt++) mma_bf16(acc[mt][nt], afrag[mt], b0, b1);
        }
#pragma unroll
        for (int mt = 0; mt < 4; mt++) {
            int r = wm * 64 + mt * 16 + gr;
            afrag[mt][0] = Al2[s][gk][r];     afrag[mt][1] = Al2[s][gk][r + 8];
            afrag[mt][2] = Al2[s][gk + 4][r]; afrag[mt][3] = Al2[s][gk + 4][r + 8];
        }
#pragma unroll
        for (int nt = 0; nt < 4; nt++) {
            int c = wn * 32 + nt * 8 + gr;
            uint32_t b0 = Bh2[s][gk][c], b1 = Bh2[s][gk + 4][c];
#pragma unroll
            for (int mt = 0; mt < 4; mt++) mma_bf16(acc[mt][nt], afrag[mt], b0, b1);
        }

        if (more) {
            int d = s ^ 1;
            stageA(d, av0, av1);
            stageB(d, bv0, bv1);
        }
        __syncthreads();
        s ^= 1;
    }

    // ---- epilogue: store C (fp16 or fp32) ----
#pragma unroll
    for (int mt = 0; mt < 4; mt++) {
        int row0 = m0 + wm * 64 + mt * 16 + gr;
        int row1 = row0 + 8;
#pragma unroll
        for (int nt = 0; nt < 4; nt++) {
            int col = wn * 32 + nt * 8 + gk * 2;
            if (Chalf) {
                if (row0 < M)
                    *reinterpret_cast<__half2*>(&Chalf[(size_t)row0 * 128 + col]) =
                        __floats2half2_rn(acc[mt][nt][0], acc[mt][nt][1]);
                if (row1 < M)
                    *reinterpret_cast<__half2*>(&Chalf[(size_t)row1 * 128 + col]) =
                        __floats2half2_rn(acc[mt][nt][2], acc[mt][nt][3]);
            } else {
                if (row0 < M)
                    *reinterpret_cast<float2*>(&C[(size_t)row0 * 128 + col]) =
                        make_float2(acc[mt][nt][0], acc[mt][nt][1]);
                if (row1 < M)
                    *reinterpret_cast<float2*>(&C[(size_t)row1 * 128 + col]) =
                        make_float2(acc[mt][nt][2], acc[mt][nt][3]);
            }
        }
    }

    // ---- fused a_src epilogue ----
    if (attp) {
        float attv[4][2];
#pragma unroll
        for (int nt = 0; nt < 4; nt++) {
            attv[nt][0] = attp[wn * 32 + nt * 8 + gk * 2];
            attv[nt][1] = attp[wn * 32 + nt * 8 + gk * 2 + 1];
        }
#pragma unroll
        for (int mt = 0; mt < 4; mt++) {
            float s0 = 0.f, s1 = 0.f;
#pragma unroll
            for (int nt = 0; nt < 4; nt++) {
                s0 += acc[mt][nt][0] * attv[nt][0] + acc[mt][nt][1] * attv[nt][1];
                s1 += acc[mt][nt][2] * attv[nt][0] + acc[mt][nt][3] * attv[nt][1];
            }
            s0 += __shfl_xor_sync(0xffffffffu, s0, 1);
            s0 += __shfl_xor_sync(0xffffffffu, s0, 2);
            s1 += __shfl_xor_sync(0xffffffffu, s1, 1);
            s1 += __shfl_xor_sync(0xffffffffu, s1, 2);
            if (gk == 0) {
                int row0 = m0 + wm * 64 + mt * 16 + gr;
                if (row0 < M) asP_out[(size_t)row0 * 8 + slot + wn] = s0;
                if (row0 + 8 < M) asP_out[(size_t)(row0 + 8) * 8 + slot + wn] = s1;
            }
        }
    }
}

// ---------------- fused gate GEMM (bf16x3): builds cat on the fly, applies sigmoid gate ----
__global__ __launch_bounds__(256) void gatefuse_kernel(int t,
                                                       const float* __restrict__ bl,
                                                       const float* __restrict__ bg,
                                                       const float* __restrict__ rg,
                                                       const float* __restrict__ gW,
                                                       const float* __restrict__ gb) {
    __shared__ uint32_t Ah2[2][8][136], Al2[2][8][136];
    __shared__ uint32_t Bh2[2][8][136], Bl2[2][8][136];
    const int tid = threadIdx.x;
    const int lane = tid & 31, warp = tid >> 5;
    const int wm = warp >> 2, wn = warp & 3;
    const int gr = lane >> 2, gk = lane & 3;
    const int m0 = blockIdx.x * 128;
    const int K = 256;

    float w0 = 1.f, w1 = 0.f;
    if (t == 0) {
        float r0 = rg[0], r1 = rg[1];
        float m = fmaxf(r0, r1);
        float e0 = __expf(r0 - m), e1 = __expf(r1 - m);
        float inv = 1.f / (e0 + e1);
        w0 = e0 * inv; w1 = e1 * inv;
    }
    const float* B = gW + (size_t)t * 32768;
    const float* gbt = gb + t * 128;
    float* fus = &g_fus[t][0];

    const int ar = tid & 127;
    const int ak8 = (tid >> 7) << 3;
    const int arow = m0 + ar;
    const int k2b = ak8 >> 1;

    auto loadA = [&](int cc) -> float4 {
        float4 v = make_float4(0.f, 0.f, 0.f, 0.f);
        if (arow >= NN) return v;
        if (cc < 128) {
            if (t == 0) {
                float4 a2 = *reinterpret_cast<const float4*>(&g_agg[2][(size_t)arow * 128 + cc]);
                float4 a4 = *reinterpret_cast<const float4*>(&g_agg[4][(size_t)arow * 128 + cc]);
                float4 b1 = *reinterpret_cast<const float4*>(&bl[128 + cc]);
                float4 b2 = *reinterpret_cast<const float4*>(&bl[256 + cc]);
#pragma unroll
                for (int e = 0; e < 4; e++)
                    (&v.x)[e] = w0 * ((&a2.x)[e] + (&b1.x)[e]) + w1 * ((&a4.x)[e] + (&b2.x)[e]);
            } else {
                float4 a0 = *reinterpret_cast<const float4*>(&g_agg[0][(size_t)arow * 128 + cc]);
                float4 b0 = *reinterpret_cast<const float4*>(&bl[cc]);
#pragma unroll
                for (int e = 0; e < 4; e++) (&v.x)[e] = (&a0.x)[e] + (&b0.x)[e];
            }
        } else {
            int c = cc - 128;
            if (t == 0) {
                float4 a3 = *reinterpret_cast<const float4*>(&g_agg[3][(size_t)arow * 128 + c]);
                float4 a5 = *reinterpret_cast<const float4*>(&g_agg[5][(size_t)arow * 128 + c]);
                float4 b1 = *reinterpret_cast<const float4*>(&bg[128 + c]);
                float4 b2 = *reinterpret_cast<const float4*>(&bg[256 + c]);
#pragma unroll
                for (int e = 0; e < 4; e++)
                    (&v.x)[e] = w0 * ((&a3.x)[e] + (&b1.x)[e]) + w1 * ((&a5.x)[e] + (&b2.x)[e]);
            } else {
                float4 a1 = *reinterpret_cast<const float4*>(&g_agg[1][(size_t)arow * 128 + c]);
                float4 b0 = *reinterpret_cast<const float4*>(&bg[c]);
#pragma unroll
                for (int e = 0; e < 4; e++) (&v.x)[e] = (&a1.x)[e] + (&b0.x)[e];
            }
        }
        return v;
    };

    auto stageA = [&](int st, float4 v0, float4 v1) {
        float h, l, h2, l2;
        h = bfhi(v0.x); l = v0.x - h; h2 = bfhi(v0.y); l2 = v0.y - h2;
        Ah2[st][k2b][ar] = packbf(h, h2); Al2[st][k2b][ar] = packbf(l, l2);
        h = bfhi(v0.z); l = v0.z - h; h2 = bfhi(v0.w); l2 = v0.w - h2;
        Ah2[st][k2b + 1][ar] = packbf(h, h2); Al2[st][k2b + 1][ar] = packbf(l, l2);
        h = bfhi(v1.x); l = v1.x - h; h2 = bfhi(v1.y); l2 = v1.y - h2;
        Ah2[st][k2b + 2][ar] = packbf(h, h2); Al2[st][k2b + 2][ar] = packbf(l, l2);
        h = bfhi(v1.z); l = v1.z - h; h2 = bfhi(v1.w); l2 = v1.w - h2;
        Ah2[st][k2b + 3][ar] = packbf(h, h2); Al2[st][k2b + 3][ar] = packbf(l, l2);
    };
    auto stageB = [&](int st, float4 r0, float4 r1) {
        uint32_t oh[4], ol[4];
#pragma unroll
        for (int e = 0; e < 4; e++) {
            float x0 = (&r0.x)[e], x1 = (&r1.x)[e];
            float h0 = bfhi(x0), h1 = bfhi(x1);
            oh[e] = packbf(h0, h1);
            ol[e] = packbf(x0 - h0, x1 - h1);
        }
        *reinterpret_cast<uint4*>(&Bh2[st][warp][lane * 4]) =
            make_uint4(oh[0], oh[1], oh[2], oh[3]);
        *reinterpret_cast<uint4*>(&Bl2[st][warp][lane * 4]) =
            make_uint4(ol[0], ol[1], ol[2], ol[3]);
    };

    float acc[4][4][4];
#pragma unroll
    for (int mt = 0; mt < 4; mt++)
#pragma unroll
        for (int nt = 0; nt < 4; nt++)
#pragma unroll
            for (int e = 0; e < 4; e++) acc[mt][nt][e] = 0.f;

    const int NIT = K >> 4;

    {
        float4 av0 = loadA(ak8), av1 = loadA(ak8 + 4);
        float4 bv0 = *reinterpret_cast<const float4*>(&B[(size_t)(2 * warp) * 128 + lane * 4]);
        float4 bv1 = *reinterpret_cast<const float4*>(&B[(size_t)(2 * warp + 1) * 128 + lane * 4]);
        stageA(0, av0, av1);
        stageB(0, bv0, bv1);
    }
    __syncthreads();

    int s = 0;
    for (int it = 0; it < NIT; it++) {
        float4 av0, av1, bv0, bv1;
        const bool more = (it + 1 < NIT);
        if (more) {
            int k0 = (it + 1) << 4;
            av0 = loadA(k0 + ak8); av1 = loadA(k0 + ak8 + 4);
            bv0 = *reinterpret_cast<const float4*>(&B[(size_t)(k0 + 2 * warp) * 128 + lane * 4]);
            bv1 = *reinterpret_cast<const float4*>(&B[(size_t)(k0 + 2 * warp + 1) * 128 + lane * 4]);
        }

        uint32_t afrag[4][4];
#pragma unroll
        for (int mt = 0; mt < 4; mt++) {
            int r = wm * 64 + mt * 16 + gr;
            afrag[mt][0] = Ah2[s][gk][r];     afrag[mt][1] = Ah2[s][gk][r + 8];
            afrag[mt][2] = Ah2[s][gk + 4][r]; afrag[mt][3] = Ah2[s][gk + 4][r + 8];
        }
#pragma unroll
        for (int nt = 0; nt < 4; nt++) {
            int c = wn * 32 + nt * 8 + gr;
            uint32_t b0 = Bh2[s][gk][c], b1 = Bh2[s][gk + 4][c];
#pragma unroll
            for (int mt = 0; mt < 4; mt++) mma_bf16(acc[mt][nt], afrag[mt], b0, b1);
        }
#pragma unroll
        for (int nt = 0; nt < 4; nt++) {
            int c = wn * 32 + nt * 8 + gr;
            uint32_t b0 = Bl2[s][gk][c], b1 = Bl2[s][gk + 4][c];
#pragma unroll
            for (int mt = 0; mt < 4; mt++) mma_bf16(acc[mt][nt], afrag[mt], b0, b1);
        }
#pragma unroll
        for (int mt = 0; mt < 4; mt++) {
            int r = wm * 64 + mt * 16 + gr;
            afrag[mt][0] = Al2[s][gk][r];     afrag[mt][1] = Al2[s][gk][r + 8];
            afrag[mt][2] = Al2[s][gk + 4][r]; afrag[mt][3] = Al2[s][gk + 4][r + 8];
        }
#pragma unroll
        for (int nt = 0; nt < 4; nt++) {
            int c = wn * 32 + nt * 8 + gr;
            uint32_t b0 = Bh2[s][gk][c], b1 = Bh2[s][gk + 4][c];
#pragma unroll
            for (int mt = 0; mt < 4; mt++) mma_bf16(acc[mt][nt], afrag[mt], b0, b1);
        }

        if (more) {
            int d = s ^ 1;
            stageA(d, av0, av1);
            stageB(d, bv0, bv1);
        }
        __syncthreads();
        s ^= 1;
    }

    // epilogue: sigmoid gate, recompute loc/glb, write fus
#pragma unroll
    for (int mt = 0; mt < 4; mt++) {
#pragma unroll
        for (int half = 0; half < 2; half++) {
            int row = m0 + wm * 64 + mt * 16 + gr + half * 8;
            if (row >= NN) continue;
#pragma unroll
            for (int nt = 0; nt < 4; nt++) {
                int col = wn * 32 + nt * 8 + gk * 2;
                float gl0 = acc[mt][nt][half * 2 + 0] + gbt[col];
                float gl1 = acc[mt][nt][half * 2 + 1] + gbt[col + 1];
                float s0 = 1.f / (1.f + __expf(-gl0));
                float s1 = 1.f / (1.f + __expf(-gl1));
                float2 loc, glb;
                if (t == 0) {
                    float2 a2 = *reinterpret_cast<const float2*>(&g_agg[2][(size_t)row * 128 + col]);
                    float2 a4 = *reinterpret_cast<const float2*>(&g_agg[4][(size_t)row * 128 + col]);
                    float2 a3 = *reinterpret_cast<const float2*>(&g_agg[3][(size_t)row * 128 + col]);
                    float2 a5 = *reinterpret_cast<const float2*>(&g_agg[5][(size_t)row * 128 + col]);
                    loc.x = w0 * (a2.x + bl[128 + col]) + w1 * (a4.x + bl[256 + col]);
                    loc.y = w0 * (a2.y + bl[128 + col + 1]) + w1 * (a4.y + bl[256 + col + 1]);
                    glb.x = w0 * (a3.x + bg[128 + col]) + w1 * (a5.x + bg[256 + col]);
                    glb.y = w0 * (a3.y + bg[128 + col + 1]) + w1 * (a5.y + bg[256 + col + 1]);
                } else {
                    float2 a0 = *reinterpret_cast<const float2*>(&g_agg[0][(size_t)row * 128 + col]);
                    float2 a1 = *reinterpret_cast<const float2*>(&g_agg[1][(size_t)row * 128 + col]);
                    loc.x = a0.x + bl[col];     loc.y = a0.y + bl[col + 1];
                    glb.x = a1.x + bg[col];     glb.y = a1.y + bg[col + 1];
                }
                float2 o;
                o.x = s0 * loc.x + (1.f - s0) * glb.x;
                o.y = s1 * loc.y + (1.f - s1) * glb.y;
                *reinterpret_cast<float2*>(&fus[(size_t)row * 128 + col]) = o;
            }
        }
    }
}

// ---------------- merged CSR build (all 3 relations) ----------------
#define ETOT (3 * EE + NN)
__global__ void zero_all_kernel() {
    int i = blockIdx.x * blockDim.x + threadIdx.x;
    if (i < 3 * NN) { (&g_deg[0][0])[i] = 0; (&g_cur[0][0])[i] = 0; }
}
__device__ __forceinline__ void edge_decode(int i, const int* eb, const int* er, const int* ef,
                                            int& rel, int& s, int& d) {
    if (i < EE) { rel = 0; s = eb[i]; d = eb[EE + i]; }
    else if (i < 2 * EE) { rel = 1; int j = i - EE; s = er[j]; d = er[EE + j]; }
    else { int j = i - 2 * EE; rel = 2;
           if (j < EE) { s = ef[j]; d = ef[EE + j]; } else { s = d = j - EE; } }
}
__global__ void count_all_kernel(const int* __restrict__ eb, const int* __restrict__ er,
                                 const int* __restrict__ ef) {
    int i = blockIdx.x * blockDim.x + threadIdx.x;
    if (i >= ETOT) return;
    int rel, s, d; edge_decode(i, eb, er, ef, rel, s, d);
    atomicAdd(&g_deg[rel][d], 1);
}
#define GSCAN ((NN + 1023) / 1024)
__global__ void scan1_all_kernel() {
    __shared__ int s[1024];
    int rel = blockIdx.x / GSCAN, blk = blockIdx.x % GSCAN;
    int tid = threadIdx.x;
    int i = blk * 1024 + tid;
    int v = (i < NN) ? g_deg[rel][i] : 0;
    s[tid] = v; __syncthreads();
    for (int d = 1; d < 1024; d <<= 1) {
        int t = (tid >= d) ? s[tid - d] : 0;
        __syncthreads();
        s[tid] += t; __syncthreads();
    }
    if (i < NN) g_off[rel][i] = s[tid] - v;
    if (tid == 1023) g_part[rel][blk] = s[1023];
}
__global__ void scan2_all_kernel() {
    __shared__ int s[128];
    int rel = blockIdx.x;
    int tid = threadIdx.x;
    int v = (tid < GSCAN) ? g_part[rel][tid] : 0;
    s[tid] = v; __syncthreads();
    for (int d = 1; d < 128; d <<= 1) {
        int t = (tid >= d) ? s[tid - d] : 0;
        __syncthreads();
        s[tid] += t; __syncthreads();
    }
    if (tid < GSCAN) g_part[rel][tid] = s[tid] - v;
    if (tid == 127) g_off[rel][NN] = s[127];
}
__global__ void scan3_all_kernel() {
    int rel = blockIdx.x / GSCAN, blk = blockIdx.x % GSCAN;
    int i = blk * 1024 + threadIdx.x;
    if (i < NN) g_off[rel][i] += g_part[rel][blk];
}
__global__ void fill_all_kernel(const int* __restrict__ eb, const int* __restrict__ er,
                                const int* __restrict__ ef) {
    int i = blockIdx.x * blockDim.x + threadIdx.x;
    if (i >= ETOT) return;
    int rel, s, d; edge_decode(i, eb, er, ef, rel, s, d);
    int pos = atomicAdd(&g_cur[rel][d], 1);
    g_csr[rel][g_off[rel][d] + pos] = s;
}

// ---------------- softmax-attention aggregation: warp per dst node, BOTH scales ----------------
// fp16 hs gathers (8B per lane per scale), unrolled x2 for MLP
__global__ void agg_kernel(int rel) {
    int node = blockIdx.x * 8 + (threadIdx.x >> 5);
    int lane = threadIdx.x & 31;
    if (node >= NN) return;
    const __half* __restrict__ hL = g_hsh[rel * 2 + 0];
    const __half* __restrict__ hG = g_hsh[rel * 2 + 1];
    const int* __restrict__ csr = g_csr[rel];
    int beg = g_off[rel][node], end = g_off[rel][node + 1];
    float adv = (lane < 8) ? g_adP[rel][(size_t)node * 8 + lane] : 0.f;
    int h = lane >> 3;
    float4 aL = make_float4(0.f, 0.f, 0.f, 0.f);
    float4 aG = make_float4(0.f, 0.f, 0.f, 0.f);
    float dL = 0.f, dG = 0.f;
    int i = beg;
    for (; i + 1 < end; i += 2) {
        int s0 = __ldg(&csr[i]), s1 = __ldg(&csr[i + 1]);
        float as0 = (lane < 8) ? __ldg(&g_asP[rel][(size_t)s0 * 8 + lane]) : 0.f;
        float as1 = (lane < 8) ? __ldg(&g_asP[rel][(size_t)s1 * 8 + lane]) : 0.f;
        __half2 l0a = *reinterpret_cast<const __half2*>(&hL[(size_t)s0 * 128 + lane * 4]);
        __half2 l0b = *reinterpret_cast<const __half2*>(&hL[(size_t)s0 * 128 + lane * 4 + 2]);
        __half2 g0a = *reinterpret_cast<const __half2*>(&hG[(size_t)s0 * 128 + lane * 4]);
        __half2 g0b = *reinterpret_cast<const __half2*>(&hG[(size_t)s0 * 128 + lane * 4 + 2]);
        __half2 l1a = *reinterpret_cast<const __half2*>(&hL[(size_t)s1 * 128 + lane * 4]);
        __half2 l1b = *reinterpret_cast<const __half2*>(&hL[(size_t)s1 * 128 + lane * 4 + 2]);
        __half2 g1a = *reinterpret_cast<const __half2*>(&hG[(size_t)s1 * 128 + lane * 4]);
        __half2 g1b = *reinterpret_cast<const __half2*>(&hG[(size_t)s1 * 128 + lane * 4 + 2]);
        float sum0 = as0 + adv, sum1 = as1 + adv;
        float sL0 = __shfl_sync(0xffffffffu, sum0, h);
        float sG0 = __shfl_sync(0xffffffffu, sum0, 4 + h);
        float sL1 = __shfl_sync(0xffffffffu, sum1, h);
        float sG1 = __shfl_sync(0xffffffffu, sum1, 4 + h);
        float eL0 = sL0 > 0.f ? sL0 : 0.2f * sL0;
        float eG0 = sG0 > 0.f ? sG0 : 0.3f * sG0;
        float eL1 = sL1 > 0.f ? sL1 : 0.2f * sL1;
        float eG1 = sG1 > 0.f ? sG1 : 0.3f * sG1;
        float wL0 = __expf(eL0), wG0 = __expf(eG0);
        float wL1 = __expf(eL1), wG1 = __expf(eG1);
        dL += wL0 + wL1; dG += wG0 + wG1;
        float2 f;
        f = __half22float2(l0a); aL.x += wL0 * f.x; aL.y += wL0 * f.y;
        f = __half22float2(l0b); aL.z += wL0 * f.x; aL.w += wL0 * f.y;
        f = __half22float2(l1a); aL.x += wL1 * f.x; aL.y += wL1 * f.y;
        f = __half22float2(l1b); aL.z += wL1 * f.x; aL.w += wL1 * f.y;
        f = __half22float2(g0a); aG.x += wG0 * f.x; aG.y += wG0 * f.y;
        f = __half22float2(g0b); aG.z += wG0 * f.x; aG.w += wG0 * f.y;
        f = __half22float2(g1a); aG.x += wG1 * f.x; aG.y += wG1 * f.y;
        f = __half22float2(g1b); aG.z += wG1 * f.x; aG.w += wG1 * f.y;
    }
    if (i < end) {
        int s0 = __ldg(&csr[i]);
        float as0 = (lane < 8) ? __ldg(&g_asP[rel][(size_t)s0 * 8 + lane]) : 0.f;
        __half2 l0a = *reinterpret_cast<const __half2*>(&hL[(size_t)s0 * 128 + lane * 4]);
        __half2 l0b = *reinterpret_cast<const __half2*>(&hL[(size_t)s0 * 128 + lane * 4 + 2]);
        __half2 g0a = *reinterpret_cast<const __half2*>(&hG[(size_t)s0 * 128 + lane * 4]);
        __half2 g0b = *reinterpret_cast<const __half2*>(&hG[(size_t)s0 * 128 + lane * 4 + 2]);
        float sum0 = as0 + adv;
        float sL0 = __shfl_sync(0xffffffffu, sum0, h);
        float sG0 = __shfl_sync(0xffffffffu, sum0, 4 + h);
        float eL0 = sL0 > 0.f ? sL0 : 0.2f * sL0;
        float eG0 = sG0 > 0.f ? sG0 : 0.3f * sG0;
        float wL0 = __expf(eL0), wG0 = __expf(eG0);
        dL += wL0; dG += wG0;
        float2 f;
        f = __half22float2(l0a); aL.x += wL0 * f.x; aL.y += wL0 * f.y;
        f = __half22float2(l0b); aL.z += wL0 * f.x; aL.w += wL0 * f.y;
        f = __half22float2(g0a); aG.x += wG0 * f.x; aG.y += wG0 * f.y;
        f = __half22float2(g0b); aG.z += wG0 * f.x; aG.w += wG0 * f.y;
    }
    float iL = 1.f / (dL + 1e-16f), iG = 1.f / (dG + 1e-16f);
    *reinterpret_cast<float4*>(&g_agg[rel * 2 + 0][(size_t)node * 128 + lane * 4]) =
        make_float4(aL.x * iL, aL.y * iL, aL.z * iL, aL.w * iL);
    *reinterpret_cast<float4*>(&g_agg[rel * 2 + 1][(size_t)node * 128 + lane * 4]) =
        make_float4(aG.x * iG, aG.y * iG, aG.z * iG, aG.w * iG);
}

// ---------------- launch ----------------
extern "C" void kernel_launch(void* const* d_in, const int* in_sizes, int n_in,
                              void* d_out, int out_size) {
    const float* x_user = (const float*)d_in[0];
    const float* x_item = (const float*)d_in[1];
    const float* Wsl = (const float*)d_in[2];
    const float* Wdl = (const float*)d_in[3];
    const float* asl = (const float*)d_in[4];
    const float* adl = (const float*)d_in[5];
    const float* bl  = (const float*)d_in[6];
    const float* Wsg = (const float*)d_in[7];
    const float* Wdg = (const float*)d_in[8];
    const float* asg = (const float*)d_in[9];
    const float* adg = (const float*)d_in[10];
    const float* bg  = (const float*)d_in[11];
    const float* gW  = (const float*)d_in[12];
    const float* gb  = (const float*)d_in[13];
    const float* oW  = (const float*)d_in[14];
    const float* rg  = (const float*)d_in[15];
    const int* ei_buys    = (const int*)d_in[16];
    const int* ei_rev     = (const int*)d_in[17];
    const int* ei_follows = (const int*)d_in[18];
    float* out = (float*)d_out;

    __half* hsh_base;
    float *asP_base, *fus_base;
    cudaGetSymbolAddress((void**)&hsh_base, g_hsh);
    cudaGetSymbolAddress((void**)&asP_base, g_asP);
    cudaGetSymbolAddress((void**)&fus_base, g_fus);

    const int GA = (NN * 32 + 255) / 256;
    const int GB = (NN + 127) / 128;

    prep_v_kernel<<<(3072 + 255) / 256, 256>>>(Wdl, Wdg, adl, adg);

    // dst-side attention logits
    compute_a_kernel<<<GA, 256>>>(x_item, 0);
    compute_a_kernel<<<GA, 256>>>(x_user, 1);
    compute_a_kernel<<<GA, 256>>>(x_user, 2);

    // CSR build (merged)
    zero_all_kernel<<<(3 * NN + 255) / 256, 256>>>();
    count_all_kernel<<<(ETOT + 255) / 256, 256>>>(ei_buys, ei_rev, ei_follows);
    scan1_all_kernel<<<3 * GSCAN, 1024>>>();
    scan2_all_kernel<<<3, 128>>>();
    scan3_all_kernel<<<3 * GSCAN, 1024>>>();
    fill_all_kernel<<<(ETOT + 255) / 256, 256>>>(ei_buys, ei_rev, ei_follows);

    // src projections hs (6 GEMMs, bf16x3, fp16 output) with fused a_src epilogue
    gemm_bf16x3_kernel<<<GB, 256>>>(x_user, Wsl + 0 * 16384, nullptr,
                                    hsh_base + (size_t)0 * NN * 128, NN, 128,
                                    asl + 0 * 128, asP_base + (size_t)0 * NN * 8, 0);
    gemm_bf16x3_kernel<<<GB, 256>>>(x_user, Wsg + 0 * 16384, nullptr,
                                    hsh_base + (size_t)1 * NN * 128, NN, 128,
                                    asg + 0 * 128, asP_base + (size_t)0 * NN * 8, 4);
    gemm_bf16x3_kernel<<<GB, 256>>>(x_item, Wsl + 1 * 16384, nullptr,
                                    hsh_base + (size_t)2 * NN * 128, NN, 128,
                                    asl + 1 * 128, asP_base + (size_t)1 * NN * 8, 0);
    gemm_bf16x3_kernel<<<GB, 256>>>(x_item, Wsg + 1 * 16384, nullptr,
                                    hsh_base + (size_t)3 * NN * 128, NN, 128,
                                    asg + 1 * 128, asP_base + (size_t)1 * NN * 8, 4);
    gemm_bf16x3_kernel<<<GB, 256>>>(x_user, Wsl + 2 * 16384, nullptr,
                                    hsh_base + (size_t)4 * NN * 128, NN, 128,
                                    asl + 2 * 128, asP_base + (size_t)2 * NN * 8, 0);
    gemm_bf16x3_kernel<<<GB, 256>>>(x_user, Wsg + 2 * 16384, nullptr,
                                    hsh_base + (size_t)5 * NN * 128, NN, 128,
                                    asg + 2 * 128, asP_base + (size_t)2 * NN * 8, 4);

    // aggregation: one relation per launch, both scales fused
    for (int r = 0; r < 3; r++)
        agg_kernel<<<(NN + 7) / 8, 256>>>(r);

    // fused gate+sigmoid+mix
    gatefuse_kernel<<<GB, 256>>>(0, bl, bg, rg, gW, gb);
    gatefuse_kernel<<<GB, 256>>>(1, bl, bg, rg, gW, gb);

    // output GEMMs (fp32 output to d_out)
    gemm_bf16x3_kernel<<<GB, 256>>>(fus_base + (size_t)0 * NN * 128, oW + 0 * 16384, out, nullptr,
                                    NN, 128, nullptr, nullptr, 0);
    gemm_bf16x3_kernel<<<GB, 256>>>(fus_base + (size_t)1 * NN * 128, oW + 1 * 16384,
                                    out + (size_t)NN * 128, nullptr, NN, 128, nullptr, nullptr, 0);
}